// round 11
// baseline (speedup 1.0000x reference)
#include <cuda_runtime.h>
#include <cuda_fp16.h>
#include <cstdint>

#define B2     2
#define CH     192
#define C3     (3*CH)
#define HEADS  4
#define HD     48
#define NSP    4096
#define L2E    1.44269504f

#define QKSTR 56   // half stride: 7 16B-chunks (odd mod 8) -> ldmatrix conflict-free
#define VSTR  72   // 9 chunks
#define CSTR  40   // conv tiles: 5 chunks
#define ORST  52   // O-staging stride (52 ≡ 20 mod 32 -> bank-bijective)

// ---------------- scratch ----------------
__device__ float  g_qkv [B2 * C3 * NSP];
__device__ float  g_att [B2 * CH * NSP];
__device__ __half g_qh  [B2 * HEADS * NSP * HD];
__device__ __half g_kh  [B2 * HEADS * NSP * HD];
__device__ __half g_vh  [B2 * CH * NSP];

// ---------------- asm helpers ----------------
__device__ __forceinline__ uint32_t sptr(const void* p) {
    return (uint32_t)__cvta_generic_to_shared(p);
}
__device__ __forceinline__ void ldsm_x4(uint32_t& r0, uint32_t& r1, uint32_t& r2, uint32_t& r3,
                                        const __half* p) {
    asm volatile("ldmatrix.sync.aligned.m8n8.x4.shared.b16 {%0,%1,%2,%3}, [%4];"
                 : "=r"(r0), "=r"(r1), "=r"(r2), "=r"(r3) : "r"(sptr(p)));
}
__device__ __forceinline__ void mma16816(float c[4],
                                         uint32_t a0, uint32_t a1, uint32_t a2, uint32_t a3,
                                         uint32_t b0, uint32_t b1) {
    asm volatile(
        "mma.sync.aligned.m16n8k16.row.col.f32.f16.f16.f32 "
        "{%0,%1,%2,%3}, {%4,%5,%6,%7}, {%8,%9}, {%0,%1,%2,%3};"
        : "+f"(c[0]), "+f"(c[1]), "+f"(c[2]), "+f"(c[3])
        : "r"(a0), "r"(a1), "r"(a2), "r"(a3), "r"(b0), "r"(b1));
}
__device__ __forceinline__ uint32_t cvt2(float hi, float lo) {
    uint32_t r;
    asm("cvt.rn.f16x2.f32 %0, %1, %2;" : "=r"(r) : "f"(hi), "f"(lo));
    return r;
}
__device__ __forceinline__ uint32_t ex2h2(uint32_t x) {
    uint32_t r;
    asm("ex2.approx.f16x2 %0, %1;" : "=r"(r) : "r"(x));
    return r;
}
__device__ __forceinline__ uint32_t hadd2(uint32_t a, uint32_t b) {
    uint32_t r;
    asm("add.rn.f16x2 %0, %1, %2;" : "=r"(r) : "r"(a), "r"(b));
    return r;
}
__device__ __forceinline__ float2 h22f2(uint32_t u) {
    __half2 h = *reinterpret_cast<__half2*>(&u);
    return __half22float2(h);
}
__device__ __forceinline__ void split4(float4 f, uint2& hi, uint2& lo) {
    hi = make_uint2(cvt2(f.y, f.x), cvt2(f.w, f.z));
    float2 g0 = h22f2(hi.x), g1 = h22f2(hi.y);
    lo = make_uint2(cvt2(f.y - g0.y, f.x - g0.x), cvt2(f.w - g1.y, f.z - g1.x));
}
__device__ __forceinline__ void cp16(const __half* smem_dst, const __half* gsrc) {
    asm volatile("cp.async.cg.shared.global [%0], [%1], 16;"
                 :: "r"(sptr(smem_dst)), "l"(gsrc));
}
__device__ __forceinline__ void cp_commit() { asm volatile("cp.async.commit_group;"); }
__device__ __forceinline__ void cp_wait0()  { asm volatile("cp.async.wait_group 0;"); }

// ---------------- 1x1 conv as split-fp16 tensor GEMM (unchanged) ----------------
__global__ void __launch_bounds__(256) conv1x1_tc_kernel(
    const float* __restrict__ X, const float* __restrict__ W,
    const float* __restrict__ bias, float* __restrict__ Cout,
    int OC, int IC)
{
    __shared__ __align__(16) __half Wh[64 * CSTR];
    __shared__ __align__(16) __half Wl[64 * CSTR];
    __shared__ __align__(16) __half Xh[64 * CSTR];
    __shared__ __align__(16) __half Xl[64 * CSTR];

    const int t    = threadIdx.x;
    const int lane = t & 31;
    const int wid  = t >> 5;
    const int o0w  = (wid & 3) * 16;
    const int n0w  = (wid >> 2) * 32;
    const int r    = lane >> 2;
    const int cc   = lane & 3;

    const int n0 = blockIdx.x * 64;
    const int o0 = blockIdx.y * 64;
    const int b  = blockIdx.z;

    const float* Xb = X + ((size_t)b * IC) * NSP + n0;

    const int nX = t & 63;
    const int cg = (t >> 6) * 4;

    float sacc[4][4];
#pragma unroll
    for (int nt = 0; nt < 4; ++nt)
#pragma unroll
        for (int e = 0; e < 4; ++e) sacc[nt][e] = 0.f;

    for (int c0 = 0; c0 < IC; c0 += 32) {
#pragma unroll
        for (int e = 0; e < 2; ++e) {
            int idx = t + e * 256;
            int o  = idx >> 3;
            int c4 = (idx & 7) * 4;
            float4 f = *(const float4*)(W + (size_t)(o0 + o) * IC + c0 + c4);
            uint2 hi, lo;
            split4(f, hi, lo);
            *(uint2*)&Wh[o * CSTR + c4] = hi;
            *(uint2*)&Wl[o * CSTR + c4] = lo;
        }
#pragma unroll
        for (int e = 0; e < 2; ++e) {
            int c = cg + e * 16;
            float4 f;
            f.x = Xb[(size_t)(c0 + c + 0) * NSP + nX];
            f.y = Xb[(size_t)(c0 + c + 1) * NSP + nX];
            f.z = Xb[(size_t)(c0 + c + 2) * NSP + nX];
            f.w = Xb[(size_t)(c0 + c + 3) * NSP + nX];
            uint2 hi, lo;
            split4(f, hi, lo);
            *(uint2*)&Xh[nX * CSTR + c] = hi;
            *(uint2*)&Xl[nX * CSTR + c] = lo;
        }
        __syncthreads();

#pragma unroll
        for (int ks = 0; ks < 2; ++ks) {
            const int arow = (o0w + (lane & 15)) * CSTR + ks * 16 + ((lane >> 4) << 3);
            uint32_t ah0, ah1, ah2, ah3, al0, al1, al2, al3;
            ldsm_x4(ah0, ah1, ah2, ah3, &Wh[arow]);
            ldsm_x4(al0, al1, al2, al3, &Wl[arow]);
#pragma unroll
            for (int p = 0; p < 2; ++p) {
                const int brow = (n0w + p * 16 + ((lane >> 4) << 3) + (lane & 7)) * CSTR
                               + ks * 16 + (lane & 8);
                uint32_t bh0, bh1, bh2, bh3, bl0, bl1, bl2, bl3;
                ldsm_x4(bh0, bh1, bh2, bh3, &Xh[brow]);
                ldsm_x4(bl0, bl1, bl2, bl3, &Xl[brow]);
                mma16816(sacc[2 * p],     ah0, ah1, ah2, ah3, bh0, bh1);
                mma16816(sacc[2 * p + 1], ah0, ah1, ah2, ah3, bh2, bh3);
                mma16816(sacc[2 * p],     ah0, ah1, ah2, ah3, bl0, bl1);
                mma16816(sacc[2 * p + 1], ah0, ah1, ah2, ah3, bl2, bl3);
                mma16816(sacc[2 * p],     al0, al1, al2, al3, bh0, bh1);
                mma16816(sacc[2 * p + 1], al0, al1, al2, al3, bh2, bh3);
            }
        }
        __syncthreads();
    }

    const int o_lo = o0 + o0w + r;
    const int o_hi = o_lo + 8;
    const float blo = bias[o_lo];
    const float bhi = bias[o_hi];
    float* out_lo = Cout + ((size_t)b * OC + o_lo) * NSP + n0 + n0w;
    float* out_hi = Cout + ((size_t)b * OC + o_hi) * NSP + n0 + n0w;
#pragma unroll
    for (int nt = 0; nt < 4; ++nt) {
        int n = nt * 8 + 2 * cc;
        *(float2*)(out_lo + n) = make_float2(sacc[nt][0] + blo, sacc[nt][1] + blo);
        *(float2*)(out_hi + n) = make_float2(sacc[nt][2] + bhi, sacc[nt][3] + bhi);
    }
}

// ---------------- 3x3 depthwise conv for V channels only -> fp16 ----------------
// grid: (B2*CH, NSP/256), block 256
__global__ void __launch_bounds__(256) dwconv_v_kernel(
    const float* __restrict__ in, const float* __restrict__ wdw,
    const float* __restrict__ bias, __half* __restrict__ vh)
{
    const int bc = blockIdx.x;
    const int c  = bc % CH;
    const int b  = bc / CH;
    const int ch = 2 * CH + c;
    const float* p = in + ((size_t)(b * C3) + ch) * NSP;

    float w9[9];
#pragma unroll
    for (int i = 0; i < 9; ++i) w9[i] = wdw[ch * 9 + i];

    const int idx = blockIdx.y * 256 + threadIdx.x;
    const int y = idx >> 6;
    const int x = idx & 63;

    float acc = bias[ch];
#pragma unroll
    for (int dy = -1; dy <= 1; ++dy) {
        int yy = y + dy;
        if (yy < 0 || yy > 63) continue;
#pragma unroll
        for (int dx = -1; dx <= 1; ++dx) {
            int xx = x + dx;
            if (xx < 0 || xx > 63) continue;
            acc += __ldg(p + yy * 64 + xx) * w9[(dy + 1) * 3 + (dx + 1)];
        }
    }
    vh[((size_t)b * CH + c) * NSP + idx] = __float2half(acc);
}

// ---------------- fused dw-conv(q,k) + L2 norm -> fp16 [bh][n][48] ----------------
// grid: (NSP/128, B2*HEADS), block 128. One thread = one pixel; 48 channels in regs.
__global__ void __launch_bounds__(128) dwqk_norm_kernel(
    const float* __restrict__ in, const float* __restrict__ wdw,
    const float* __restrict__ bias, __half* __restrict__ qh, __half* __restrict__ kh,
    const float* __restrict__ temp)
{
    const int bh   = blockIdx.y;
    const int b    = bh >> 2;
    const int head = bh & 3;
    const int n    = blockIdx.x * 128 + threadIdx.x;
    const int y    = n >> 6;
    const int x    = n & 63;
    const bool ym = (y > 0), yp = (y < 63);
    const bool xm = (x > 0), xp = (x < 63);

#pragma unroll
    for (int which = 0; which < 2; ++which) {
        const int ch0 = which * CH + head * HD;
        float v[HD];
        float s = 0.f;
#pragma unroll
        for (int d = 0; d < HD; ++d) {
            const int ch = ch0 + d;
            const float* p  = in + ((size_t)(b * C3) + ch) * NSP + n;
            const float* w9 = wdw + ch * 9;
            float acc = bias[ch];
            acc += p[0] * w9[4];
            if (xm) acc += p[-1] * w9[3];
            if (xp) acc += p[ 1] * w9[5];
            if (ym) {
                acc += p[-64] * w9[1];
                if (xm) acc += p[-65] * w9[0];
                if (xp) acc += p[-63] * w9[2];
            }
            if (yp) {
                acc += p[64] * w9[7];
                if (xm) acc += p[63] * w9[6];
                if (xp) acc += p[65] * w9[8];
            }
            v[d] = acc;
            s += acc * acc;
        }
        const float sc = (which ? 1.0f : temp[head] * L2E) / fmaxf(sqrtf(s), 1e-12f);
        __half* o = (which ? kh : qh) + ((size_t)bh * NSP + n) * HD;
#pragma unroll
        for (int g = 0; g < 6; ++g) {
            float a0 = v[g * 8 + 0] * sc, a1 = v[g * 8 + 1] * sc;
            float a2 = v[g * 8 + 2] * sc, a3 = v[g * 8 + 3] * sc;
            float a4 = v[g * 8 + 4] * sc, a5 = v[g * 8 + 5] * sc;
            float a6 = v[g * 8 + 6] * sc, a7 = v[g * 8 + 7] * sc;
            *(uint4*)(o + g * 8) = make_uint4(cvt2(a1, a0), cvt2(a3, a2),
                                              cvt2(a5, a4), cvt2(a7, a6));
        }
    }
}

// ---------------- flash attention: R9 structure (best), bias folded into sacc init ----
// BQ=128, 8 warps = 4(M=32) x 2(J=32). Single prefetch commit per tile at the top.
__global__ void __launch_bounds__(256, 2) attn_kernel(
    const __half* __restrict__ qh, const __half* __restrict__ kh,
    const __half* __restrict__ vh, const float* __restrict__ temp,
    float* __restrict__ out)
{
    // arena: Qs [0,14336) | Ks0 [14336,21504) | Ks1 [21504,28672) | Vs0/1 [28672,42496) | lred [42496,43008)
    __shared__ __align__(16) char arena[43008];
    __half* Qs = (__half*)arena;
    __half* KsBuf[2] = { (__half*)(arena + 14336), (__half*)(arena + 21504) };
    __half* VsBuf[2] = { (__half*)(arena + 28672), (__half*)(arena + 35584) };
    float*  lred = (float*)(arena + 42496);
    float*  Ored = (float*)arena;        // epilogue overlay over Qs/Ks regions

    const int t    = threadIdx.x;
    const int lane = t & 31;
    const int wid  = t >> 5;
    const int wi   = wid & 3;
    const int wj   = wid >> 2;
    const int i0   = wi * 32;
    const int r    = lane >> 2;
    const int cc   = lane & 3;

    const int bh   = blockIdx.y;
    const int b    = bh >> 2;
    const int head = bh & 3;
    const int n0   = blockIdx.x * 128;

    const __half* qb = qh + (size_t)bh * NSP * HD;
    const __half* kb = kh + (size_t)bh * NSP * HD;
    const __half* vb = vh + ((size_t)b * CH + head * HD) * NSP;
    const float   cbias = fabsf(temp[head]) * L2E;

    // ---- prologue: cp.async Q + K0 + V0 ----
#pragma unroll
    for (int e = 0; e < 3; ++e) {
        int ch = t + e * 256, row = ch / 6, c = (ch % 6) * 8;
        cp16(&Qs[row * QKSTR + c], qb + ((size_t)(n0 + row)) * HD + c);
    }
    {
        int row = t / 6, c = (t % 6) * 8;
        cp16(&KsBuf[0][row * QKSTR + c], kb + (size_t)row * HD + c);
    }
    if (t < 128) {
        int ch = t + 256, row = ch / 6, c = (ch % 6) * 8;
        cp16(&KsBuf[0][row * QKSTR + c], kb + (size_t)row * HD + c);
    }
    {
        int row = t >> 3, c = (t & 7) * 8;
        cp16(&VsBuf[0][row * VSTR + c], vb + (size_t)row * NSP + c);
    }
    if (t < 128) {
        int ch = t + 256, row = ch >> 3, c = (ch & 7) * 8;
        cp16(&VsBuf[0][row * VSTR + c], vb + (size_t)row * NSP + c);
    }
    cp_commit();

    float oacc[2][6][4];
#pragma unroll
    for (int mt = 0; mt < 2; ++mt)
#pragma unroll
        for (int nt = 0; nt < 6; ++nt)
#pragma unroll
            for (int e = 0; e < 4; ++e) oacc[mt][nt][e] = 0.f;
    float l_lo[2] = {0.f, 0.f}, l_hi[2] = {0.f, 0.f};

    uint32_t qa[2][3][4];

    const int krow0 = t / 6,          kc0 = (t % 6) * 8;
    const int krow1 = (t + 256) / 6,  kc1 = ((t + 256) % 6) * 8;
    const int vrow0 = t >> 3,         vc0 = (t & 7) * 8;
    const int vrow1 = (t + 256) >> 3, vc1 = ((t + 256) & 7) * 8;

    for (int it = 0; it < NSP / 64; ++it) {
        const int cur = it & 1;
        const __half* Kc = KsBuf[cur];
        const __half* Vc = VsBuf[cur];
        const bool has_next = (it < NSP / 64 - 1);

        cp_wait0();
        __syncthreads();

        if (it == 0) {
#pragma unroll
            for (int mt = 0; mt < 2; ++mt)
#pragma unroll
                for (int ks = 0; ks < 3; ++ks)
                    ldsm_x4(qa[mt][ks][0], qa[mt][ks][1], qa[mt][ks][2], qa[mt][ks][3],
                            &Qs[(i0 + mt * 16 + (lane & 15)) * QKSTR + ks * 16 + ((lane >> 4) << 3)]);
        }

        // ---- prefetch K(it+1), V(it+1) as ONE commit group (full-tile distance) ----
        if (has_next) {
            const int nb = cur ^ 1;
            const int m0n = (it + 1) * 64;
            cp16(&KsBuf[nb][krow0 * QKSTR + kc0], kb + ((size_t)(m0n + krow0)) * HD + kc0);
            if (t < 128)
                cp16(&KsBuf[nb][krow1 * QKSTR + kc1], kb + ((size_t)(m0n + krow1)) * HD + kc1);
            cp16(&VsBuf[nb][vrow0 * VSTR + vc0], vb + (size_t)vrow0 * NSP + m0n + vc0);
            if (t < 128)
                cp16(&VsBuf[nb][vrow1 * VSTR + vc1], vb + (size_t)vrow1 * NSP + m0n + vc1);
            cp_commit();
        }

        // ---- S = Q K^T for the warp's 32-key j-half (sacc pre-biased with -cbias) ----
        float sacc[2][4][4];
#pragma unroll
        for (int mt = 0; mt < 2; ++mt)
#pragma unroll
            for (int jj = 0; jj < 4; ++jj)
#pragma unroll
                for (int e = 0; e < 4; ++e) sacc[mt][jj][e] = -cbias;

#pragma unroll
        for (int ks = 0; ks < 3; ++ks) {
#pragma unroll
            for (int p = 0; p < 2; ++p) {
                uint32_t b0, b1, b2, b3;
                int row = wj * 32 + p * 16 + ((lane >> 4) << 3) + (lane & 7);
                int col = ks * 16 + (lane & 8);
                ldsm_x4(b0, b1, b2, b3, &Kc[row * QKSTR + col]);
#pragma unroll
                for (int mt = 0; mt < 2; ++mt) {
                    mma16816(sacc[mt][2 * p],     qa[mt][ks][0], qa[mt][ks][1],
                                                  qa[mt][ks][2], qa[mt][ks][3], b0, b1);
                    mma16816(sacc[mt][2 * p + 1], qa[mt][ks][0], qa[mt][ks][1],
                                                  qa[mt][ks][2], qa[mt][ks][3], b2, b3);
                }
            }
        }

        // ---- softmax in registers: P = exp2(S) (bias folded into init) ----
        uint32_t plo[2][4], phi[2][4];
#pragma unroll
        for (int mt = 0; mt < 2; ++mt) {
            uint32_t sum_lo = 0, sum_hi = 0;
#pragma unroll
            for (int jj = 0; jj < 4; ++jj) {
                plo[mt][jj] = ex2h2(cvt2(sacc[mt][jj][1], sacc[mt][jj][0]));
                phi[mt][jj] = ex2h2(cvt2(sacc[mt][jj][3], sacc[mt][jj][2]));
                sum_lo = hadd2(sum_lo, plo[mt][jj]);
                sum_hi = hadd2(sum_hi, phi[mt][jj]);
            }
            float2 f0 = h22f2(sum_lo); l_lo[mt] += f0.x + f0.y;
            float2 f1 = h22f2(sum_hi); l_hi[mt] += f1.x + f1.y;
        }

        // ---- O += P V^T over the warp's 32 keys; both M-tiles share V frags ----
#pragma unroll
        for (int nt = 0; nt < 6; ++nt) {
            uint32_t b0, b1, b2, b3;
            ldsm_x4(b0, b1, b2, b3,
                    &Vc[(nt * 8 + (lane & 7)) * VSTR + wj * 32 + ((lane >> 3) & 3) * 8]);
#pragma unroll
            for (int mt = 0; mt < 2; ++mt) {
                mma16816(oacc[mt][nt], plo[mt][0], phi[mt][0], plo[mt][1], phi[mt][1], b0, b1);
                mma16816(oacc[mt][nt], plo[mt][2], phi[mt][2], plo[mt][3], phi[mt][3], b2, b3);
            }
        }
        __syncthreads();
    }

    // ---- epilogue: reduce l in quad; wj=1 stages; wj=0 combines + stores ----
#pragma unroll
    for (int mt = 0; mt < 2; ++mt) {
        l_lo[mt] += __shfl_xor_sync(0xffffffffu, l_lo[mt], 1);
        l_lo[mt] += __shfl_xor_sync(0xffffffffu, l_lo[mt], 2);
        l_hi[mt] += __shfl_xor_sync(0xffffffffu, l_hi[mt], 1);
        l_hi[mt] += __shfl_xor_sync(0xffffffffu, l_hi[mt], 2);
    }
    if (wj == 1) {
#pragma unroll
        for (int mt = 0; mt < 2; ++mt) {
            const int ib = i0 + mt * 16;
            if (cc == 0) {
                lred[ib + r]     = l_lo[mt];
                lred[ib + r + 8] = l_hi[mt];
            }
#pragma unroll
            for (int nt = 0; nt < 6; ++nt) {
                int d = nt * 8 + 2 * cc;
                *(float2*)&Ored[(ib + r) * ORST + d]     = make_float2(oacc[mt][nt][0], oacc[mt][nt][1]);
                *(float2*)&Ored[(ib + r + 8) * ORST + d] = make_float2(oacc[mt][nt][2], oacc[mt][nt][3]);
            }
        }
    }
    __syncthreads();
    if (wj == 0) {
        float* ob = out + ((size_t)(b * CH) + head * HD) * NSP + n0;
#pragma unroll
        for (int mt = 0; mt < 2; ++mt) {
            const int ib = i0 + mt * 16;
            const float linv_lo = 1.f / (l_lo[mt] + lred[ib + r]);
            const float linv_hi = 1.f / (l_hi[mt] + lred[ib + r + 8]);
#pragma unroll
            for (int nt = 0; nt < 6; ++nt) {
                int d = nt * 8 + 2 * cc;
                float2 p0 = *(const float2*)&Ored[(ib + r) * ORST + d];
                float2 p1 = *(const float2*)&Ored[(ib + r + 8) * ORST + d];
                ob[(size_t)d * NSP + ib + r]           = (oacc[mt][nt][0] + p0.x) * linv_lo;
                ob[(size_t)(d + 1) * NSP + ib + r]     = (oacc[mt][nt][1] + p0.y) * linv_lo;
                ob[(size_t)d * NSP + ib + r + 8]       = (oacc[mt][nt][2] + p1.x) * linv_hi;
                ob[(size_t)(d + 1) * NSP + ib + r + 8] = (oacc[mt][nt][3] + p1.y) * linv_hi;
            }
        }
    }
}

// ---------------- launcher ----------------
extern "C" void kernel_launch(void* const* d_in, const int* in_sizes, int n_in,
                              void* d_out, int out_size)
{
    const float* x      = (const float*)d_in[0];
    const float* w_qkv  = (const float*)d_in[1];
    const float* b_qkv  = (const float*)d_in[2];
    const float* w_dw   = (const float*)d_in[3];
    const float* b_dw   = (const float*)d_in[4];
    const float* w_proj = (const float*)d_in[5];
    const float* b_proj = (const float*)d_in[6];
    const float* temp   = (const float*)d_in[7];
    float* out = (float*)d_out;

    float*  qkv1; cudaGetSymbolAddress((void**)&qkv1, g_qkv);
    float*  att;  cudaGetSymbolAddress((void**)&att,  g_att);
    __half* qhp;  cudaGetSymbolAddress((void**)&qhp,  g_qh);
    __half* khp;  cudaGetSymbolAddress((void**)&khp,  g_kh);
    __half* vhp;  cudaGetSymbolAddress((void**)&vhp,  g_vh);

    conv1x1_tc_kernel<<<dim3(NSP / 64, C3 / 64, B2), 256>>>(x, w_qkv, b_qkv, qkv1, C3, CH);
    dwconv_v_kernel<<<dim3(B2 * CH, NSP / 256), 256>>>(qkv1, w_dw, b_dw, vhp);
    dwqk_norm_kernel<<<dim3(NSP / 128, B2 * HEADS), 128>>>(qkv1, w_dw, b_dw, qhp, khp, temp);
    attn_kernel<<<dim3(NSP / 128, B2 * HEADS), 256>>>(qhp, khp, vhp, temp, att);
    conv1x1_tc_kernel<<<dim3(NSP / 64, CH / 64, B2), 256>>>(att, w_proj, b_proj, out, CH, CH);
}

// round 12
// speedup vs baseline: 1.3468x; 1.3468x over previous
#include <cuda_runtime.h>
#include <cuda_fp16.h>
#include <cstdint>

#define B2     2
#define CH     192
#define C3     (3*CH)
#define HEADS  4
#define HD     48
#define NSP    4096
#define L2E    1.44269504f

#define QKSTR 56   // half stride: 7 16B-chunks (odd mod 8) -> ldmatrix conflict-free
#define VSTR  72   // 9 chunks
#define CSTR  40   // conv tiles: 5 chunks
#define ORST  52   // O-staging stride (52 ≡ 20 mod 32 -> bank-bijective)

// ---------------- scratch ----------------
__device__ float  g_qkv [B2 * C3 * NSP];
__device__ float  g_qkv2[B2 * C3 * NSP];
__device__ float  g_att [B2 * CH * NSP];
__device__ __half g_qh  [B2 * HEADS * NSP * HD];
__device__ __half g_kh  [B2 * HEADS * NSP * HD];
__device__ __half g_vh  [B2 * CH * NSP];

// ---------------- asm helpers ----------------
__device__ __forceinline__ uint32_t sptr(const void* p) {
    return (uint32_t)__cvta_generic_to_shared(p);
}
__device__ __forceinline__ void ldsm_x4(uint32_t& r0, uint32_t& r1, uint32_t& r2, uint32_t& r3,
                                        const __half* p) {
    asm volatile("ldmatrix.sync.aligned.m8n8.x4.shared.b16 {%0,%1,%2,%3}, [%4];"
                 : "=r"(r0), "=r"(r1), "=r"(r2), "=r"(r3) : "r"(sptr(p)));
}
__device__ __forceinline__ void mma16816(float c[4],
                                         uint32_t a0, uint32_t a1, uint32_t a2, uint32_t a3,
                                         uint32_t b0, uint32_t b1) {
    asm volatile(
        "mma.sync.aligned.m16n8k16.row.col.f32.f16.f16.f32 "
        "{%0,%1,%2,%3}, {%4,%5,%6,%7}, {%8,%9}, {%0,%1,%2,%3};"
        : "+f"(c[0]), "+f"(c[1]), "+f"(c[2]), "+f"(c[3])
        : "r"(a0), "r"(a1), "r"(a2), "r"(a3), "r"(b0), "r"(b1));
}
__device__ __forceinline__ uint32_t cvt2(float hi, float lo) {
    uint32_t r;
    asm("cvt.rn.f16x2.f32 %0, %1, %2;" : "=r"(r) : "f"(hi), "f"(lo));
    return r;
}
__device__ __forceinline__ uint32_t ex2h2(uint32_t x) {
    uint32_t r;
    asm("ex2.approx.f16x2 %0, %1;" : "=r"(r) : "r"(x));
    return r;
}
__device__ __forceinline__ uint32_t hadd2(uint32_t a, uint32_t b) {
    uint32_t r;
    asm("add.rn.f16x2 %0, %1, %2;" : "=r"(r) : "r"(a), "r"(b));
    return r;
}
__device__ __forceinline__ float2 h22f2(uint32_t u) {
    __half2 h = *reinterpret_cast<__half2*>(&u);
    return __half22float2(h);
}
__device__ __forceinline__ void split4(float4 f, uint2& hi, uint2& lo) {
    hi = make_uint2(cvt2(f.y, f.x), cvt2(f.w, f.z));
    float2 g0 = h22f2(hi.x), g1 = h22f2(hi.y);
    lo = make_uint2(cvt2(f.y - g0.y, f.x - g0.x), cvt2(f.w - g1.y, f.z - g1.x));
}
__device__ __forceinline__ void cp16(const __half* smem_dst, const __half* gsrc) {
    asm volatile("cp.async.cg.shared.global [%0], [%1], 16;"
                 :: "r"(sptr(smem_dst)), "l"(gsrc));
}
__device__ __forceinline__ void cp_commit() { asm volatile("cp.async.commit_group;"); }
__device__ __forceinline__ void cp_wait0()  { asm volatile("cp.async.wait_group 0;"); }

// ---------------- 1x1 conv as split-fp16 tensor GEMM (unchanged) ----------------
__global__ void __launch_bounds__(256) conv1x1_tc_kernel(
    const float* __restrict__ X, const float* __restrict__ W,
    const float* __restrict__ bias, float* __restrict__ Cout,
    int OC, int IC)
{
    __shared__ __align__(16) __half Wh[64 * CSTR];
    __shared__ __align__(16) __half Wl[64 * CSTR];
    __shared__ __align__(16) __half Xh[64 * CSTR];
    __shared__ __align__(16) __half Xl[64 * CSTR];

    const int t    = threadIdx.x;
    const int lane = t & 31;
    const int wid  = t >> 5;
    const int o0w  = (wid & 3) * 16;
    const int n0w  = (wid >> 2) * 32;
    const int r    = lane >> 2;
    const int cc   = lane & 3;

    const int n0 = blockIdx.x * 64;
    const int o0 = blockIdx.y * 64;
    const int b  = blockIdx.z;

    const float* Xb = X + ((size_t)b * IC) * NSP + n0;

    const int nX = t & 63;
    const int cg = (t >> 6) * 4;

    float sacc[4][4];
#pragma unroll
    for (int nt = 0; nt < 4; ++nt)
#pragma unroll
        for (int e = 0; e < 4; ++e) sacc[nt][e] = 0.f;

    for (int c0 = 0; c0 < IC; c0 += 32) {
#pragma unroll
        for (int e = 0; e < 2; ++e) {
            int idx = t + e * 256;
            int o  = idx >> 3;
            int c4 = (idx & 7) * 4;
            float4 f = *(const float4*)(W + (size_t)(o0 + o) * IC + c0 + c4);
            uint2 hi, lo;
            split4(f, hi, lo);
            *(uint2*)&Wh[o * CSTR + c4] = hi;
            *(uint2*)&Wl[o * CSTR + c4] = lo;
        }
#pragma unroll
        for (int e = 0; e < 2; ++e) {
            int c = cg + e * 16;
            float4 f;
            f.x = Xb[(size_t)(c0 + c + 0) * NSP + nX];
            f.y = Xb[(size_t)(c0 + c + 1) * NSP + nX];
            f.z = Xb[(size_t)(c0 + c + 2) * NSP + nX];
            f.w = Xb[(size_t)(c0 + c + 3) * NSP + nX];
            uint2 hi, lo;
            split4(f, hi, lo);
            *(uint2*)&Xh[nX * CSTR + c] = hi;
            *(uint2*)&Xl[nX * CSTR + c] = lo;
        }
        __syncthreads();

#pragma unroll
        for (int ks = 0; ks < 2; ++ks) {
            const int arow = (o0w + (lane & 15)) * CSTR + ks * 16 + ((lane >> 4) << 3);
            uint32_t ah0, ah1, ah2, ah3, al0, al1, al2, al3;
            ldsm_x4(ah0, ah1, ah2, ah3, &Wh[arow]);
            ldsm_x4(al0, al1, al2, al3, &Wl[arow]);
#pragma unroll
            for (int p = 0; p < 2; ++p) {
                const int brow = (n0w + p * 16 + ((lane >> 4) << 3) + (lane & 7)) * CSTR
                               + ks * 16 + (lane & 8);
                uint32_t bh0, bh1, bh2, bh3, bl0, bl1, bl2, bl3;
                ldsm_x4(bh0, bh1, bh2, bh3, &Xh[brow]);
                ldsm_x4(bl0, bl1, bl2, bl3, &Xl[brow]);
                mma16816(sacc[2 * p],     ah0, ah1, ah2, ah3, bh0, bh1);
                mma16816(sacc[2 * p + 1], ah0, ah1, ah2, ah3, bh2, bh3);
                mma16816(sacc[2 * p],     ah0, ah1, ah2, ah3, bl0, bl1);
                mma16816(sacc[2 * p + 1], ah0, ah1, ah2, ah3, bl2, bl3);
                mma16816(sacc[2 * p],     al0, al1, al2, al3, bh0, bh1);
                mma16816(sacc[2 * p + 1], al0, al1, al2, al3, bh2, bh3);
            }
        }
        __syncthreads();
    }

    const int o_lo = o0 + o0w + r;
    const int o_hi = o_lo + 8;
    const float blo = bias[o_lo];
    const float bhi = bias[o_hi];
    float* out_lo = Cout + ((size_t)b * OC + o_lo) * NSP + n0 + n0w;
    float* out_hi = Cout + ((size_t)b * OC + o_hi) * NSP + n0 + n0w;
#pragma unroll
    for (int nt = 0; nt < 4; ++nt) {
        int n = nt * 8 + 2 * cc;
        *(float2*)(out_lo + n) = make_float2(sacc[nt][0] + blo, sacc[nt][1] + blo);
        *(float2*)(out_hi + n) = make_float2(sacc[nt][2] + bhi, sacc[nt][3] + bhi);
    }
}

// ---------------- 3x3 depthwise conv; v channels emitted as fp16 (R9 version) --------
__global__ void __launch_bounds__(256) dwconv_kernel(
    const float* __restrict__ in, const float* __restrict__ wdw,
    const float* __restrict__ bias, float* __restrict__ out, __half* __restrict__ vh)
{
    const int bc = blockIdx.x;
    const int ch = bc % C3;
    const int b  = bc / C3;
    const float* p = in + (size_t)bc * NSP;

    float w9[9];
#pragma unroll
    for (int i = 0; i < 9; ++i) w9[i] = wdw[ch * 9 + i];

    const int idx = blockIdx.y * 256 + threadIdx.x;
    const int y = idx >> 6;
    const int x = idx & 63;

    float acc = bias[ch];
#pragma unroll
    for (int dy = -1; dy <= 1; ++dy) {
        int yy = y + dy;
        if (yy < 0 || yy > 63) continue;
#pragma unroll
        for (int dx = -1; dx <= 1; ++dx) {
            int xx = x + dx;
            if (xx < 0 || xx > 63) continue;
            acc += __ldg(p + yy * 64 + xx) * w9[(dy + 1) * 3 + (dx + 1)];
        }
    }
    if (ch < 2 * CH) {
        out[(size_t)bc * NSP + idx] = acc;
    } else {
        vh[((size_t)b * CH + (ch - 2 * CH)) * NSP + idx] = __float2half(acc);
    }
}

// ---------------- single-pass L2 norm -> fp16 [bh][n][48]; q and k via z-dim ----------
__global__ void __launch_bounds__(128) normh_kernel(
    const float* __restrict__ qkv, __half* __restrict__ qh, __half* __restrict__ kh,
    const float* __restrict__ temp)
{
    const int which = blockIdx.z;        // 0 = q, 1 = k
    const int bh    = blockIdx.y;
    const int b     = bh >> 2;
    const int head  = bh & 3;
    const int n     = blockIdx.x * 128 + threadIdx.x;

    const float* p = qkv + ((size_t)(b * C3) + which * CH + head * HD) * NSP + n;

    float v[HD];
    float s = 0.f;
#pragma unroll
    for (int d = 0; d < HD; ++d) {
        v[d] = p[(size_t)d * NSP];
        s += v[d] * v[d];
    }
    const float sc = (which ? 1.0f : temp[head] * L2E) / fmaxf(sqrtf(s), 1e-12f);

    __half* o = (which ? kh : qh) + ((size_t)bh * NSP + n) * HD;
#pragma unroll
    for (int g = 0; g < 6; ++g) {
        float a0 = v[g * 8 + 0] * sc, a1 = v[g * 8 + 1] * sc;
        float a2 = v[g * 8 + 2] * sc, a3 = v[g * 8 + 3] * sc;
        float a4 = v[g * 8 + 4] * sc, a5 = v[g * 8 + 5] * sc;
        float a6 = v[g * 8 + 6] * sc, a7 = v[g * 8 + 7] * sc;
        *(uint4*)(o + g * 8) = make_uint4(cvt2(a1, a0), cvt2(a3, a2), cvt2(a5, a4), cvt2(a7, a6));
    }
}

// ---------------- flash attention: R9 pipeline + S(it)/O(it-1) ILP, triple-V ----------
// BQ=128, 8 warps = 4(M=32) x 2(J=32). Single prefetch commit per tile at the top
// (R9 structure). V triple-buffered (3rd buffer overlays dead Q region) so O-mma of
// tile it-1 can run after S-mma of tile it with P carried in registers.
__global__ void __launch_bounds__(256, 2) attn_kernel(
    const __half* __restrict__ qh, const __half* __restrict__ kh,
    const __half* __restrict__ vh, const float* __restrict__ temp,
    float* __restrict__ out)
{
    // arena: Qs [0,14336) (V2 overlays [0,6912) from tile 1 on) |
    //        Ks0 [14336,21504) | Ks1 [21504,28672) |
    //        Vs0 [28672,35584) | Vs1 [35584,42496) | lred [42496,43008)
    __shared__ __align__(16) char arena[43008];
    __half* Qs = (__half*)arena;
    __half* KsBuf[2] = { (__half*)(arena + 14336), (__half*)(arena + 21504) };
    __half* V0 = (__half*)(arena + 28672);
    __half* V1 = (__half*)(arena + 35584);
    __half* V2 = (__half*)arena;                      // overlays Qs (dead after it==0)
    float*  lred = (float*)(arena + 42496);
    float*  Ored = (float*)arena;                     // epilogue overlay

    const int t    = threadIdx.x;
    const int lane = t & 31;
    const int wid  = t >> 5;
    const int wi   = wid & 3;
    const int wj   = wid >> 2;
    const int i0   = wi * 32;
    const int r    = lane >> 2;
    const int cc   = lane & 3;

    const int bh   = blockIdx.y;
    const int b    = bh >> 2;
    const int head = bh & 3;
    const int n0   = blockIdx.x * 128;

    const __half* qb = qh + (size_t)bh * NSP * HD;
    const __half* kb = kh + (size_t)bh * NSP * HD;
    const __half* vb = vh + ((size_t)b * CH + head * HD) * NSP;
    const float   cbias = fabsf(temp[head]) * L2E;

    // ---- prologue: cp.async Q + K0 + V0 (one group) ----
#pragma unroll
    for (int e = 0; e < 3; ++e) {
        int ch = t + e * 256, row = ch / 6, c = (ch % 6) * 8;
        cp16(&Qs[row * QKSTR + c], qb + ((size_t)(n0 + row)) * HD + c);
    }
    {
        int row = t / 6, c = (t % 6) * 8;
        cp16(&KsBuf[0][row * QKSTR + c], kb + (size_t)row * HD + c);
    }
    if (t < 128) {
        int ch = t + 256, row = ch / 6, c = (ch % 6) * 8;
        cp16(&KsBuf[0][row * QKSTR + c], kb + (size_t)row * HD + c);
    }
    {
        int row = t >> 3, c = (t & 7) * 8;
        cp16(&V0[row * VSTR + c], vb + (size_t)row * NSP + c);
    }
    if (t < 128) {
        int ch = t + 256, row = ch >> 3, c = (ch & 7) * 8;
        cp16(&V0[row * VSTR + c], vb + (size_t)row * NSP + c);
    }
    cp_commit();

    float oacc[2][6][4];
#pragma unroll
    for (int mt = 0; mt < 2; ++mt)
#pragma unroll
        for (int nt = 0; nt < 6; ++nt)
#pragma unroll
            for (int e = 0; e < 4; ++e) oacc[mt][nt][e] = 0.f;
    float l_lo[2] = {0.f, 0.f}, l_hi[2] = {0.f, 0.f};

    uint32_t qa[2][3][4];
    uint32_t plo[2][4], phi[2][4];     // P(it-1), carried across the tile boundary

    const int krow0 = t / 6,          kc0 = (t % 6) * 8;
    const int krow1 = (t + 256) / 6,  kc1 = ((t + 256) % 6) * 8;
    const int vrow0 = t >> 3,         vc0 = (t & 7) * 8;
    const int vrow1 = (t + 256) >> 3, vc1 = ((t + 256) & 7) * 8;

    int v_cur = 0, v_nxt = 1, v_prv = 2;   // rotating V buffer indices (mod 3)

    for (int it = 0; it < NSP / 64; ++it) {
        const int cur = it & 1;
        const __half* Kc = KsBuf[cur];
        const bool has_next = (it < NSP / 64 - 1);

        cp_wait0();
        __syncthreads();

        if (it == 0) {
#pragma unroll
            for (int mt = 0; mt < 2; ++mt)
#pragma unroll
                for (int ks = 0; ks < 3; ++ks)
                    ldsm_x4(qa[mt][ks][0], qa[mt][ks][1], qa[mt][ks][2], qa[mt][ks][3],
                            &Qs[(i0 + mt * 16 + (lane & 15)) * QKSTR + ks * 16 + ((lane >> 4) << 3)]);
        }

        // ---- prefetch K(it+1), V(it+1) as ONE commit group (full-tile distance) ----
        if (has_next) {
            __half* Kn = KsBuf[cur ^ 1];
            __half* Vn = (v_nxt == 0) ? V0 : (v_nxt == 1) ? V1 : V2;
            const int m0n = (it + 1) * 64;
            cp16(&Kn[krow0 * QKSTR + kc0], kb + ((size_t)(m0n + krow0)) * HD + kc0);
            if (t < 128)
                cp16(&Kn[krow1 * QKSTR + kc1], kb + ((size_t)(m0n + krow1)) * HD + kc1);
            cp16(&Vn[vrow0 * VSTR + vc0], vb + (size_t)vrow0 * NSP + m0n + vc0);
            if (t < 128)
                cp16(&Vn[vrow1 * VSTR + vc1], vb + (size_t)vrow1 * NSP + m0n + vc1);
            cp_commit();
        }

        // ---- S = Q K^T for tile it (sacc pre-biased with -cbias) ----
        float sacc[2][4][4];
#pragma unroll
        for (int mt = 0; mt < 2; ++mt)
#pragma unroll
            for (int jj = 0; jj < 4; ++jj)
#pragma unroll
                for (int e = 0; e < 4; ++e) sacc[mt][jj][e] = -cbias;

#pragma unroll
        for (int ks = 0; ks < 3; ++ks) {
#pragma unroll
            for (int p = 0; p < 2; ++p) {
                uint32_t b0, b1, b2, b3;
                int row = wj * 32 + p * 16 + ((lane >> 4) << 3) + (lane & 7);
                int col = ks * 16 + (lane & 8);
                ldsm_x4(b0, b1, b2, b3, &Kc[row * QKSTR + col]);
#pragma unroll
                for (int mt = 0; mt < 2; ++mt) {
                    mma16816(sacc[mt][2 * p],     qa[mt][ks][0], qa[mt][ks][1],
                                                  qa[mt][ks][2], qa[mt][ks][3], b0, b1);
                    mma16816(sacc[mt][2 * p + 1], qa[mt][ks][0], qa[mt][ks][1],
                                                  qa[mt][ks][2], qa[mt][ks][3], b2, b3);
                }
            }
        }

        // ---- O += P(it-1) V(it-1)^T — independent of fresh sacc (ILP) ----
        if (it > 0) {
            const __half* Vp = (v_prv == 0) ? V0 : (v_prv == 1) ? V1 : V2;
#pragma unroll
            for (int nt = 0; nt < 6; ++nt) {
                uint32_t b0, b1, b2, b3;
                ldsm_x4(b0, b1, b2, b3,
                        &Vp[(nt * 8 + (lane & 7)) * VSTR + wj * 32 + ((lane >> 3) & 3) * 8]);
#pragma unroll
                for (int mt = 0; mt < 2; ++mt) {
                    mma16816(oacc[mt][nt], plo[mt][0], phi[mt][0], plo[mt][1], phi[mt][1], b0, b1);
                    mma16816(oacc[mt][nt], plo[mt][2], phi[mt][2], plo[mt][3], phi[mt][3], b2, b3);
                }
            }
        }

        // ---- softmax(it): P = exp2(S) (bias folded into init) ----
#pragma unroll
        for (int mt = 0; mt < 2; ++mt) {
            uint32_t sum_lo = 0, sum_hi = 0;
#pragma unroll
            for (int jj = 0; jj < 4; ++jj) {
                plo[mt][jj] = ex2h2(cvt2(sacc[mt][jj][1], sacc[mt][jj][0]));
                phi[mt][jj] = ex2h2(cvt2(sacc[mt][jj][3], sacc[mt][jj][2]));
                sum_lo = hadd2(sum_lo, plo[mt][jj]);
                sum_hi = hadd2(sum_hi, phi[mt][jj]);
            }
            float2 f0 = h22f2(sum_lo); l_lo[mt] += f0.x + f0.y;
            float2 f1 = h22f2(sum_hi); l_hi[mt] += f1.x + f1.y;
        }

        // rotate V buffer indices
        v_prv = v_cur; v_cur = v_nxt; v_nxt = (v_nxt == 2) ? 0 : v_nxt + 1;
    }

    // ---- drain: O += P(63) V(63)^T  (tile 63's V is in buffer v_prv = 0) ----
    {
        const __half* Vp = (v_prv == 0) ? V0 : (v_prv == 1) ? V1 : V2;
#pragma unroll
        for (int nt = 0; nt < 6; ++nt) {
            uint32_t b0, b1, b2, b3;
            ldsm_x4(b0, b1, b2, b3,
                    &Vp[(nt * 8 + (lane & 7)) * VSTR + wj * 32 + ((lane >> 3) & 3) * 8]);
#pragma unroll
            for (int mt = 0; mt < 2; ++mt) {
                mma16816(oacc[mt][nt], plo[mt][0], phi[mt][0], plo[mt][1], phi[mt][1], b0, b1);
                mma16816(oacc[mt][nt], plo[mt][2], phi[mt][2], plo[mt][3], phi[mt][3], b2, b3);
            }
        }
    }

    // ---- epilogue: reduce l in quad; wj=1 stages; wj=0 combines + stores ----
#pragma unroll
    for (int mt = 0; mt < 2; ++mt) {
        l_lo[mt] += __shfl_xor_sync(0xffffffffu, l_lo[mt], 1);
        l_lo[mt] += __shfl_xor_sync(0xffffffffu, l_lo[mt], 2);
        l_hi[mt] += __shfl_xor_sync(0xffffffffu, l_hi[mt], 1);
        l_hi[mt] += __shfl_xor_sync(0xffffffffu, l_hi[mt], 2);
    }
    __syncthreads();   // all K/V smem reads done before Ored overlay writes
    if (wj == 1) {
#pragma unroll
        for (int mt = 0; mt < 2; ++mt) {
            const int ib = i0 + mt * 16;
            if (cc == 0) {
                lred[ib + r]     = l_lo[mt];
                lred[ib + r + 8] = l_hi[mt];
            }
#pragma unroll
            for (int nt = 0; nt < 6; ++nt) {
                int d = nt * 8 + 2 * cc;
                *(float2*)&Ored[(ib + r) * ORST + d]     = make_float2(oacc[mt][nt][0], oacc[mt][nt][1]);
                *(float2*)&Ored[(ib + r + 8) * ORST + d] = make_float2(oacc[mt][nt][2], oacc[mt][nt][3]);
            }
        }
    }
    __syncthreads();
    if (wj == 0) {
        float* ob = out + ((size_t)(b * CH) + head * HD) * NSP + n0;
#pragma unroll
        for (int mt = 0; mt < 2; ++mt) {
            const int ib = i0 + mt * 16;
            const float linv_lo = 1.f / (l_lo[mt] + lred[ib + r]);
            const float linv_hi = 1.f / (l_hi[mt] + lred[ib + r + 8]);
#pragma unroll
            for (int nt = 0; nt < 6; ++nt) {
                int d = nt * 8 + 2 * cc;
                float2 p0 = *(const float2*)&Ored[(ib + r) * ORST + d];
                float2 p1 = *(const float2*)&Ored[(ib + r + 8) * ORST + d];
                ob[(size_t)d * NSP + ib + r]           = (oacc[mt][nt][0] + p0.x) * linv_lo;
                ob[(size_t)(d + 1) * NSP + ib + r]     = (oacc[mt][nt][1] + p0.y) * linv_lo;
                ob[(size_t)d * NSP + ib + r + 8]       = (oacc[mt][nt][2] + p1.x) * linv_hi;
                ob[(size_t)(d + 1) * NSP + ib + r + 8] = (oacc[mt][nt][3] + p1.y) * linv_hi;
            }
        }
    }
}

// ---------------- launcher (R9 kernel set) ----------------
extern "C" void kernel_launch(void* const* d_in, const int* in_sizes, int n_in,
                              void* d_out, int out_size)
{
    const float* x      = (const float*)d_in[0];
    const float* w_qkv  = (const float*)d_in[1];
    const float* b_qkv  = (const float*)d_in[2];
    const float* w_dw   = (const float*)d_in[3];
    const float* b_dw   = (const float*)d_in[4];
    const float* w_proj = (const float*)d_in[5];
    const float* b_proj = (const float*)d_in[6];
    const float* temp   = (const float*)d_in[7];
    float* out = (float*)d_out;

    float*  qkv1; cudaGetSymbolAddress((void**)&qkv1, g_qkv);
    float*  qkv2; cudaGetSymbolAddress((void**)&qkv2, g_qkv2);
    float*  att;  cudaGetSymbolAddress((void**)&att,  g_att);
    __half* qhp;  cudaGetSymbolAddress((void**)&qhp,  g_qh);
    __half* khp;  cudaGetSymbolAddress((void**)&khp,  g_kh);
    __half* vhp;  cudaGetSymbolAddress((void**)&vhp,  g_vh);

    conv1x1_tc_kernel<<<dim3(NSP / 64, C3 / 64, B2), 256>>>(x, w_qkv, b_qkv, qkv1, C3, CH);
    dwconv_kernel<<<dim3(B2 * C3, NSP / 256), 256>>>(qkv1, w_dw, b_dw, qkv2, vhp);
    normh_kernel<<<dim3(NSP / 128, B2 * HEADS, 2), 128>>>(qkv2, qhp, khp, temp);
    attn_kernel<<<dim3(NSP / 128, B2 * HEADS), 256>>>(qhp, khp, vhp, temp, att);
    conv1x1_tc_kernel<<<dim3(NSP / 64, CH / 64, B2), 256>>>(att, w_proj, b_proj, out, CH, CH);
}

// round 13
// speedup vs baseline: 1.3644x; 1.0131x over previous
#include <cuda_runtime.h>
#include <cuda_fp16.h>
#include <cstdint>

#define B2     2
#define CH     192
#define C3     (3*CH)
#define HEADS  4
#define HD     48
#define NSP    4096
#define L2E    1.44269504f
#define NSPLIT 2
#define KPS    (NSP / NSPLIT)   // keys per split

#define QKSTR 56   // half stride: 7 16B-chunks (odd mod 8) -> ldmatrix conflict-free
#define VSTR  72   // 9 chunks
#define CSTR  40   // conv tiles: 5 chunks

// ---------------- scratch ----------------
__device__ float  g_qkv [B2 * C3 * NSP];
__device__ float  g_qkv2[B2 * C3 * NSP];
__device__ float  g_att [B2 * CH * NSP];
__device__ float  g_opart[NSPLIT * B2 * CH * NSP];      // unnormalized O per split
__device__ float  g_lpart[NSPLIT * B2 * HEADS * NSP];   // partial softmax denom
__device__ __half g_qh  [B2 * HEADS * NSP * HD];
__device__ __half g_kh  [B2 * HEADS * NSP * HD];
__device__ __half g_vh  [B2 * CH * NSP];

// ---------------- asm helpers ----------------
__device__ __forceinline__ uint32_t sptr(const void* p) {
    return (uint32_t)__cvta_generic_to_shared(p);
}
__device__ __forceinline__ void ldsm_x4(uint32_t& r0, uint32_t& r1, uint32_t& r2, uint32_t& r3,
                                        const __half* p) {
    asm volatile("ldmatrix.sync.aligned.m8n8.x4.shared.b16 {%0,%1,%2,%3}, [%4];"
                 : "=r"(r0), "=r"(r1), "=r"(r2), "=r"(r3) : "r"(sptr(p)));
}
__device__ __forceinline__ void mma16816(float c[4],
                                         uint32_t a0, uint32_t a1, uint32_t a2, uint32_t a3,
                                         uint32_t b0, uint32_t b1) {
    asm volatile(
        "mma.sync.aligned.m16n8k16.row.col.f32.f16.f16.f32 "
        "{%0,%1,%2,%3}, {%4,%5,%6,%7}, {%8,%9}, {%0,%1,%2,%3};"
        : "+f"(c[0]), "+f"(c[1]), "+f"(c[2]), "+f"(c[3])
        : "r"(a0), "r"(a1), "r"(a2), "r"(a3), "r"(b0), "r"(b1));
}
__device__ __forceinline__ uint32_t cvt2(float hi, float lo) {
    uint32_t r;
    asm("cvt.rn.f16x2.f32 %0, %1, %2;" : "=r"(r) : "f"(hi), "f"(lo));
    return r;
}
__device__ __forceinline__ uint32_t ex2h2(uint32_t x) {
    uint32_t r;
    asm("ex2.approx.f16x2 %0, %1;" : "=r"(r) : "r"(x));
    return r;
}
__device__ __forceinline__ uint32_t hadd2(uint32_t a, uint32_t b) {
    uint32_t r;
    asm("add.rn.f16x2 %0, %1, %2;" : "=r"(r) : "r"(a), "r"(b));
    return r;
}
__device__ __forceinline__ float2 h22f2(uint32_t u) {
    __half2 h = *reinterpret_cast<__half2*>(&u);
    return __half22float2(h);
}
__device__ __forceinline__ void split4(float4 f, uint2& hi, uint2& lo) {
    hi = make_uint2(cvt2(f.y, f.x), cvt2(f.w, f.z));
    float2 g0 = h22f2(hi.x), g1 = h22f2(hi.y);
    lo = make_uint2(cvt2(f.y - g0.y, f.x - g0.x), cvt2(f.w - g1.y, f.z - g1.x));
}
__device__ __forceinline__ void cp16(const __half* smem_dst, const __half* gsrc) {
    asm volatile("cp.async.cg.shared.global [%0], [%1], 16;"
                 :: "r"(sptr(smem_dst)), "l"(gsrc));
}
__device__ __forceinline__ void cp_commit() { asm volatile("cp.async.commit_group;"); }
__device__ __forceinline__ void cp_wait0()  { asm volatile("cp.async.wait_group 0;"); }

// ---------------- 1x1 conv as split-fp16 tensor GEMM (unchanged) ----------------
__global__ void __launch_bounds__(256) conv1x1_tc_kernel(
    const float* __restrict__ X, const float* __restrict__ W,
    const float* __restrict__ bias, float* __restrict__ Cout,
    int OC, int IC)
{
    __shared__ __align__(16) __half Wh[64 * CSTR];
    __shared__ __align__(16) __half Wl[64 * CSTR];
    __shared__ __align__(16) __half Xh[64 * CSTR];
    __shared__ __align__(16) __half Xl[64 * CSTR];

    const int t    = threadIdx.x;
    const int lane = t & 31;
    const int wid  = t >> 5;
    const int o0w  = (wid & 3) * 16;
    const int n0w  = (wid >> 2) * 32;
    const int r    = lane >> 2;
    const int cc   = lane & 3;

    const int n0 = blockIdx.x * 64;
    const int o0 = blockIdx.y * 64;
    const int b  = blockIdx.z;

    const float* Xb = X + ((size_t)b * IC) * NSP + n0;

    const int nX = t & 63;
    const int cg = (t >> 6) * 4;

    float sacc[4][4];
#pragma unroll
    for (int nt = 0; nt < 4; ++nt)
#pragma unroll
        for (int e = 0; e < 4; ++e) sacc[nt][e] = 0.f;

    for (int c0 = 0; c0 < IC; c0 += 32) {
#pragma unroll
        for (int e = 0; e < 2; ++e) {
            int idx = t + e * 256;
            int o  = idx >> 3;
            int c4 = (idx & 7) * 4;
            float4 f = *(const float4*)(W + (size_t)(o0 + o) * IC + c0 + c4);
            uint2 hi, lo;
            split4(f, hi, lo);
            *(uint2*)&Wh[o * CSTR + c4] = hi;
            *(uint2*)&Wl[o * CSTR + c4] = lo;
        }
#pragma unroll
        for (int e = 0; e < 2; ++e) {
            int c = cg + e * 16;
            float4 f;
            f.x = Xb[(size_t)(c0 + c + 0) * NSP + nX];
            f.y = Xb[(size_t)(c0 + c + 1) * NSP + nX];
            f.z = Xb[(size_t)(c0 + c + 2) * NSP + nX];
            f.w = Xb[(size_t)(c0 + c + 3) * NSP + nX];
            uint2 hi, lo;
            split4(f, hi, lo);
            *(uint2*)&Xh[nX * CSTR + c] = hi;
            *(uint2*)&Xl[nX * CSTR + c] = lo;
        }
        __syncthreads();

#pragma unroll
        for (int ks = 0; ks < 2; ++ks) {
            const int arow = (o0w + (lane & 15)) * CSTR + ks * 16 + ((lane >> 4) << 3);
            uint32_t ah0, ah1, ah2, ah3, al0, al1, al2, al3;
            ldsm_x4(ah0, ah1, ah2, ah3, &Wh[arow]);
            ldsm_x4(al0, al1, al2, al3, &Wl[arow]);
#pragma unroll
            for (int p = 0; p < 2; ++p) {
                const int brow = (n0w + p * 16 + ((lane >> 4) << 3) + (lane & 7)) * CSTR
                               + ks * 16 + (lane & 8);
                uint32_t bh0, bh1, bh2, bh3, bl0, bl1, bl2, bl3;
                ldsm_x4(bh0, bh1, bh2, bh3, &Xh[brow]);
                ldsm_x4(bl0, bl1, bl2, bl3, &Xl[brow]);
                mma16816(sacc[2 * p],     ah0, ah1, ah2, ah3, bh0, bh1);
                mma16816(sacc[2 * p + 1], ah0, ah1, ah2, ah3, bh2, bh3);
                mma16816(sacc[2 * p],     ah0, ah1, ah2, ah3, bl0, bl1);
                mma16816(sacc[2 * p + 1], ah0, ah1, ah2, ah3, bl2, bl3);
                mma16816(sacc[2 * p],     al0, al1, al2, al3, bh0, bh1);
                mma16816(sacc[2 * p + 1], al0, al1, al2, al3, bh2, bh3);
            }
        }
        __syncthreads();
    }

    const int o_lo = o0 + o0w + r;
    const int o_hi = o_lo + 8;
    const float blo = bias[o_lo];
    const float bhi = bias[o_hi];
    float* out_lo = Cout + ((size_t)b * OC + o_lo) * NSP + n0 + n0w;
    float* out_hi = Cout + ((size_t)b * OC + o_hi) * NSP + n0 + n0w;
#pragma unroll
    for (int nt = 0; nt < 4; ++nt) {
        int n = nt * 8 + 2 * cc;
        *(float2*)(out_lo + n) = make_float2(sacc[nt][0] + blo, sacc[nt][1] + blo);
        *(float2*)(out_hi + n) = make_float2(sacc[nt][2] + bhi, sacc[nt][3] + bhi);
    }
}

// ---------------- 3x3 depthwise conv; v channels emitted as fp16 ----------------
__global__ void __launch_bounds__(256) dwconv_kernel(
    const float* __restrict__ in, const float* __restrict__ wdw,
    const float* __restrict__ bias, float* __restrict__ out, __half* __restrict__ vh)
{
    const int bc = blockIdx.x;
    const int ch = bc % C3;
    const int b  = bc / C3;
    const float* p = in + (size_t)bc * NSP;

    float w9[9];
#pragma unroll
    for (int i = 0; i < 9; ++i) w9[i] = wdw[ch * 9 + i];

    const int idx = blockIdx.y * 256 + threadIdx.x;
    const int y = idx >> 6;
    const int x = idx & 63;

    float acc = bias[ch];
#pragma unroll
    for (int dy = -1; dy <= 1; ++dy) {
        int yy = y + dy;
        if (yy < 0 || yy > 63) continue;
#pragma unroll
        for (int dx = -1; dx <= 1; ++dx) {
            int xx = x + dx;
            if (xx < 0 || xx > 63) continue;
            acc += __ldg(p + yy * 64 + xx) * w9[(dy + 1) * 3 + (dx + 1)];
        }
    }
    if (ch < 2 * CH) {
        out[(size_t)bc * NSP + idx] = acc;
    } else {
        vh[((size_t)b * CH + (ch - 2 * CH)) * NSP + idx] = __float2half(acc);
    }
}

// ---------------- single-pass L2 norm -> fp16 [bh][n][48]; q and k via z-dim ----------
__global__ void __launch_bounds__(128) normh_kernel(
    const float* __restrict__ qkv, __half* __restrict__ qh, __half* __restrict__ kh,
    const float* __restrict__ temp)
{
    const int which = blockIdx.z;        // 0 = q, 1 = k
    const int bh    = blockIdx.y;
    const int b     = bh >> 2;
    const int head  = bh & 3;
    const int n     = blockIdx.x * 128 + threadIdx.x;

    const float* p = qkv + ((size_t)(b * C3) + which * CH + head * HD) * NSP + n;

    float v[HD];
    float s = 0.f;
#pragma unroll
    for (int d = 0; d < HD; ++d) {
        v[d] = p[(size_t)d * NSP];
        s += v[d] * v[d];
    }
    const float sc = (which ? 1.0f : temp[head] * L2E) / fmaxf(sqrtf(s), 1e-12f);

    __half* o = (which ? kh : qh) + ((size_t)bh * NSP + n) * HD;
#pragma unroll
    for (int g = 0; g < 6; ++g) {
        float a0 = v[g * 8 + 0] * sc, a1 = v[g * 8 + 1] * sc;
        float a2 = v[g * 8 + 2] * sc, a3 = v[g * 8 + 3] * sc;
        float a4 = v[g * 8 + 4] * sc, a5 = v[g * 8 + 5] * sc;
        float a6 = v[g * 8 + 6] * sc, a7 = v[g * 8 + 7] * sc;
        *(uint4*)(o + g * 8) = make_uint4(cvt2(a1, a0), cvt2(a3, a2), cvt2(a5, a4), cvt2(a7, a6));
    }
}

// ---------------- flash attention: split-K x2, R6 warp layout (low regs) -------------
// grid: (NSP/128, B2*HEADS*NSPLIT), block 256 (8 warps, warp w owns rows [16w,16w+16)).
// Each CTA covers keys [split*2048, split*2048+2048). Writes unnormalized O + l.
__global__ void __launch_bounds__(256, 3) attn_kernel(
    const __half* __restrict__ qh, const __half* __restrict__ kh,
    const __half* __restrict__ vh, const float* __restrict__ temp,
    float* __restrict__ opart, float* __restrict__ lpart)
{
    __shared__ __align__(16) __half Qs[128 * QKSTR];   // 14.0 KB
    __shared__ __align__(16) __half Ks[2][64 * QKSTR]; // 14.0 KB
    __shared__ __align__(16) __half Vs[2][HD * VSTR];  // 13.5 KB

    const int t    = threadIdx.x;
    const int lane = t & 31;
    const int wid  = t >> 5;
    const int i0   = wid * 16;
    const int r    = lane >> 2;
    const int cc   = lane & 3;

    const int ys    = blockIdx.y;
    const int bh    = ys >> 1;
    const int split = ys & 1;
    const int b     = bh >> 2;
    const int head  = bh & 3;
    const int n0    = blockIdx.x * 128;

    const __half* qb = qh + (size_t)bh * NSP * HD;
    const __half* kb = kh + (size_t)bh * NSP * HD + (size_t)split * KPS * HD;
    const __half* vb = vh + ((size_t)b * CH + head * HD) * NSP + split * KPS;
    const float   cbias = fabsf(temp[head]) * L2E;

    // ---- prologue: cp.async Q (768 chunks) + K0 (384) + V0 (384) ----
#pragma unroll
    for (int e = 0; e < 3; ++e) {
        int ch = t + e * 256, row = ch / 6, c = (ch % 6) * 8;
        cp16(&Qs[row * QKSTR + c], qb + ((size_t)(n0 + row)) * HD + c);
    }
    {
        int row = t / 6, c = (t % 6) * 8;
        cp16(&Ks[0][row * QKSTR + c], kb + (size_t)row * HD + c);
    }
    if (t < 128) {
        int ch = t + 256, row = ch / 6, c = (ch % 6) * 8;
        cp16(&Ks[0][row * QKSTR + c], kb + (size_t)row * HD + c);
    }
    {
        int row = t >> 3, c = (t & 7) * 8;
        cp16(&Vs[0][row * VSTR + c], vb + (size_t)row * NSP + c);
    }
    if (t < 128) {
        int ch = t + 256, row = ch >> 3, c = (ch & 7) * 8;
        cp16(&Vs[0][row * VSTR + c], vb + (size_t)row * NSP + c);
    }
    cp_commit();

    float oacc[6][4];
#pragma unroll
    for (int nt = 0; nt < 6; ++nt)
#pragma unroll
        for (int e = 0; e < 4; ++e) oacc[nt][e] = 0.f;
    float l_lo = 0.f, l_hi = 0.f;

    uint32_t qa[3][4];   // Q fragments, loaded once

    const int krow0 = t / 6,          kc0 = (t % 6) * 8;
    const int krow1 = (t + 256) / 6,  kc1 = ((t + 256) % 6) * 8;
    const int vrow0 = t >> 3,         vc0 = (t & 7) * 8;
    const int vrow1 = (t + 256) >> 3, vc1 = ((t + 256) & 7) * 8;

    for (int it = 0; it < KPS / 64; ++it) {
        const int cur = it & 1;
        const __half* Kc = Ks[cur];
        const __half* Vc = Vs[cur];
        const bool has_next = (it < KPS / 64 - 1);

        cp_wait0();
        __syncthreads();

        if (it == 0) {
#pragma unroll
            for (int ks = 0; ks < 3; ++ks)
                ldsm_x4(qa[ks][0], qa[ks][1], qa[ks][2], qa[ks][3],
                        &Qs[(i0 + (lane & 15)) * QKSTR + ks * 16 + ((lane >> 4) << 3)]);
        }

        if (has_next) {
            const int nb = cur ^ 1;
            const int m0n = (it + 1) * 64;
            cp16(&Ks[nb][krow0 * QKSTR + kc0], kb + ((size_t)(m0n + krow0)) * HD + kc0);
            if (t < 128)
                cp16(&Ks[nb][krow1 * QKSTR + kc1], kb + ((size_t)(m0n + krow1)) * HD + kc1);
            cp16(&Vs[nb][vrow0 * VSTR + vc0], vb + (size_t)vrow0 * NSP + m0n + vc0);
            if (t < 128)
                cp16(&Vs[nb][vrow1 * VSTR + vc1], vb + (size_t)vrow1 * NSP + m0n + vc1);
            cp_commit();
        }

        // ---- S = Q K^T (warp: 16i x 64j) ----
        float sacc[8][4];
#pragma unroll
        for (int nt = 0; nt < 8; ++nt)
#pragma unroll
            for (int e = 0; e < 4; ++e) sacc[nt][e] = 0.f;

#pragma unroll
        for (int ks = 0; ks < 3; ++ks) {
#pragma unroll
            for (int p = 0; p < 4; ++p) {
                uint32_t b0, b1, b2, b3;
                int row = p * 16 + ((lane >> 4) << 3) + (lane & 7);
                int col = ks * 16 + (lane & 8);
                ldsm_x4(b0, b1, b2, b3, &Kc[row * QKSTR + col]);
                mma16816(sacc[2 * p],     qa[ks][0], qa[ks][1], qa[ks][2], qa[ks][3], b0, b1);
                mma16816(sacc[2 * p + 1], qa[ks][0], qa[ks][1], qa[ks][2], qa[ks][3], b2, b3);
            }
        }

        // ---- softmax in registers: P = exp2(S - c) ----
        uint32_t plo[8], phi[8];
        uint32_t sum_lo = 0, sum_hi = 0;
#pragma unroll
        for (int nt = 0; nt < 8; ++nt) {
            plo[nt] = ex2h2(cvt2(sacc[nt][1] - cbias, sacc[nt][0] - cbias));
            phi[nt] = ex2h2(cvt2(sacc[nt][3] - cbias, sacc[nt][2] - cbias));
            sum_lo = hadd2(sum_lo, plo[nt]);
            sum_hi = hadd2(sum_hi, phi[nt]);
        }
        {
            float2 f0 = h22f2(sum_lo); l_lo += f0.x + f0.y;
            float2 f1 = h22f2(sum_hi); l_hi += f1.x + f1.y;
        }

        // ---- O += P V^T (warp: 16i x 48d over k=64) ----
#pragma unroll
        for (int nt = 0; nt < 6; ++nt) {
#pragma unroll
            for (int h = 0; h < 2; ++h) {
                uint32_t b0, b1, b2, b3;
                ldsm_x4(b0, b1, b2, b3,
                        &Vc[(nt * 8 + (lane & 7)) * VSTR + h * 32 + ((lane >> 3) & 3) * 8]);
                mma16816(oacc[nt], plo[4 * h + 0], phi[4 * h + 0],
                                   plo[4 * h + 1], phi[4 * h + 1], b0, b1);
                mma16816(oacc[nt], plo[4 * h + 2], phi[4 * h + 2],
                                   plo[4 * h + 3], phi[4 * h + 3], b2, b3);
            }
        }
        __syncthreads();
    }

    // ---- epilogue: per-warp, write UNNORMALIZED O + partial l ----
    l_lo += __shfl_xor_sync(0xffffffffu, l_lo, 1);
    l_lo += __shfl_xor_sync(0xffffffffu, l_lo, 2);
    l_hi += __shfl_xor_sync(0xffffffffu, l_hi, 1);
    l_hi += __shfl_xor_sync(0xffffffffu, l_hi, 2);

    float* ob = opart + ((size_t)(split * B2 + b) * CH + head * HD) * NSP + n0;
    float* lb = lpart + ((size_t)(split * B2 * HEADS + bh)) * NSP + n0;
    if (cc == 0) {
        lb[i0 + r]     = l_lo;
        lb[i0 + r + 8] = l_hi;
    }
#pragma unroll
    for (int nt = 0; nt < 6; ++nt) {
        int d = nt * 8 + 2 * cc;
        ob[(size_t)d * NSP + i0 + r]           = oacc[nt][0];
        ob[(size_t)(d + 1) * NSP + i0 + r]     = oacc[nt][1];
        ob[(size_t)d * NSP + i0 + r + 8]       = oacc[nt][2];
        ob[(size_t)(d + 1) * NSP + i0 + r + 8] = oacc[nt][3];
    }
}

// ---------------- combine split-K partials: att = (O0+O1)/(l0+l1) ----------------
// grid: (B2*CH, NSP/256), block 256
__global__ void __launch_bounds__(256) combine_kernel(
    const float* __restrict__ opart, const float* __restrict__ lpart,
    float* __restrict__ att)
{
    const int bc   = blockIdx.x;
    const int b    = bc / CH;
    const int c    = bc % CH;
    const int head = c / HD;
    const int bh   = b * HEADS + head;
    const int n    = blockIdx.y * 256 + threadIdx.x;

    const float l0 = lpart[(size_t)bh * NSP + n];
    const float l1 = lpart[((size_t)(B2 * HEADS) + bh) * NSP + n];
    const float o0 = opart[(size_t)bc * NSP + n];
    const float o1 = opart[((size_t)(B2 * CH) + bc) * NSP + n];
    att[(size_t)bc * NSP + n] = (o0 + o1) / (l0 + l1);
}

// ---------------- launcher ----------------
extern "C" void kernel_launch(void* const* d_in, const int* in_sizes, int n_in,
                              void* d_out, int out_size)
{
    const float* x      = (const float*)d_in[0];
    const float* w_qkv  = (const float*)d_in[1];
    const float* b_qkv  = (const float*)d_in[2];
    const float* w_dw   = (const float*)d_in[3];
    const float* b_dw   = (const float*)d_in[4];
    const float* w_proj = (const float*)d_in[5];
    const float* b_proj = (const float*)d_in[6];
    const float* temp   = (const float*)d_in[7];
    float* out = (float*)d_out;

    float*  qkv1;  cudaGetSymbolAddress((void**)&qkv1,  g_qkv);
    float*  qkv2;  cudaGetSymbolAddress((void**)&qkv2,  g_qkv2);
    float*  att;   cudaGetSymbolAddress((void**)&att,   g_att);
    float*  opart; cudaGetSymbolAddress((void**)&opart, g_opart);
    float*  lpart; cudaGetSymbolAddress((void**)&lpart, g_lpart);
    __half* qhp;   cudaGetSymbolAddress((void**)&qhp,   g_qh);
    __half* khp;   cudaGetSymbolAddress((void**)&khp,   g_kh);
    __half* vhp;   cudaGetSymbolAddress((void**)&vhp,   g_vh);

    conv1x1_tc_kernel<<<dim3(NSP / 64, C3 / 64, B2), 256>>>(x, w_qkv, b_qkv, qkv1, C3, CH);
    dwconv_kernel<<<dim3(B2 * C3, NSP / 256), 256>>>(qkv1, w_dw, b_dw, qkv2, vhp);
    normh_kernel<<<dim3(NSP / 128, B2 * HEADS, 2), 128>>>(qkv2, qhp, khp, temp);
    attn_kernel<<<dim3(NSP / 128, B2 * HEADS * NSPLIT), 256>>>(qhp, khp, vhp, temp, opart, lpart);
    combine_kernel<<<dim3(B2 * CH, NSP / 256), 256>>>(opart, lpart, att);
    conv1x1_tc_kernel<<<dim3(NSP / 64, CH / 64, B2), 256>>>(att, w_proj, b_proj, out, CH, CH);
}

// round 14
// speedup vs baseline: 1.3988x; 1.0252x over previous
#include <cuda_runtime.h>
#include <cuda_fp16.h>
#include <cstdint>

#define B2     2
#define CH     192
#define C3     (3*CH)
#define HEADS  4
#define HD     48
#define NSP    4096
#define L2E    1.44269504f

#define QKSTR 56   // half stride: 7 16B-chunks (odd mod 8) -> ldmatrix conflict-free
#define VSTR  72   // 9 chunks
#define CSTR  40   // conv tiles: 5 chunks
#define ORST  52   // O-staging stride (52 ≡ 20 mod 32 -> bank-bijective)

// ---------------- scratch ----------------
__device__ float  g_qkv [B2 * C3 * NSP];
__device__ float  g_qkv2[B2 * C3 * NSP];
__device__ __half g_xh  [B2 * NSP * CH];   // x fp16 hi, [b][n][c]
__device__ __half g_xl  [B2 * NSP * CH];   // x fp16 lo residual
__device__ __half g_ah  [B2 * NSP * CH];   // attn out fp16 hi, [b][n][c]
__device__ __half g_al  [B2 * NSP * CH];   // attn out fp16 lo residual
__device__ __half g_qh  [B2 * HEADS * NSP * HD];
__device__ __half g_kh  [B2 * HEADS * NSP * HD];
__device__ __half g_vh  [B2 * CH * NSP];

// ---------------- asm helpers ----------------
__device__ __forceinline__ uint32_t sptr(const void* p) {
    return (uint32_t)__cvta_generic_to_shared(p);
}
__device__ __forceinline__ void ldsm_x4(uint32_t& r0, uint32_t& r1, uint32_t& r2, uint32_t& r3,
                                        const __half* p) {
    asm volatile("ldmatrix.sync.aligned.m8n8.x4.shared.b16 {%0,%1,%2,%3}, [%4];"
                 : "=r"(r0), "=r"(r1), "=r"(r2), "=r"(r3) : "r"(sptr(p)));
}
__device__ __forceinline__ void mma16816(float c[4],
                                         uint32_t a0, uint32_t a1, uint32_t a2, uint32_t a3,
                                         uint32_t b0, uint32_t b1) {
    asm volatile(
        "mma.sync.aligned.m16n8k16.row.col.f32.f16.f16.f32 "
        "{%0,%1,%2,%3}, {%4,%5,%6,%7}, {%8,%9}, {%0,%1,%2,%3};"
        : "+f"(c[0]), "+f"(c[1]), "+f"(c[2]), "+f"(c[3])
        : "r"(a0), "r"(a1), "r"(a2), "r"(a3), "r"(b0), "r"(b1));
}
__device__ __forceinline__ uint32_t cvt2(float hi, float lo) {
    uint32_t r;
    asm("cvt.rn.f16x2.f32 %0, %1, %2;" : "=r"(r) : "f"(hi), "f"(lo));
    return r;
}
__device__ __forceinline__ uint32_t ex2h2(uint32_t x) {
    uint32_t r;
    asm("ex2.approx.f16x2 %0, %1;" : "=r"(r) : "r"(x));
    return r;
}
__device__ __forceinline__ uint32_t hadd2(uint32_t a, uint32_t b) {
    uint32_t r;
    asm("add.rn.f16x2 %0, %1, %2;" : "=r"(r) : "r"(a), "r"(b));
    return r;
}
__device__ __forceinline__ float2 h22f2(uint32_t u) {
    __half2 h = *reinterpret_cast<__half2*>(&u);
    return __half22float2(h);
}
__device__ __forceinline__ void split4(float4 f, uint2& hi, uint2& lo) {
    hi = make_uint2(cvt2(f.y, f.x), cvt2(f.w, f.z));
    float2 g0 = h22f2(hi.x), g1 = h22f2(hi.y);
    lo = make_uint2(cvt2(f.y - g0.y, f.x - g0.x), cvt2(f.w - g1.y, f.z - g1.x));
}
__device__ __forceinline__ void cp16(const __half* smem_dst, const __half* gsrc) {
    asm volatile("cp.async.cg.shared.global [%0], [%1], 16;"
                 :: "r"(sptr(smem_dst)), "l"(gsrc));
}
__device__ __forceinline__ void cp_commit() { asm volatile("cp.async.commit_group;"); }
__device__ __forceinline__ void cp_wait0()  { asm volatile("cp.async.wait_group 0;"); }

// ---------------- x prep: fp32 [b][c][n] -> fp16 hi/lo [b][n][c] ----------------
// grid: (NSP/64, CH/32, B2), block 256
__global__ void __launch_bounds__(256) xprep_kernel(
    const float* __restrict__ X, __half* __restrict__ Xh, __half* __restrict__ Xl)
{
    __shared__ float xs[32][65];

    const int t  = threadIdx.x;
    const int n0 = blockIdx.x * 64;
    const int c0 = blockIdx.y * 32;
    const int b  = blockIdx.z;

    // load 32c x 64n tile (coalesced along n)
    {
        const int n = t & 63;
        const int cg = (t >> 6) * 8;
#pragma unroll
        for (int e = 0; e < 8; ++e) {
            int c = cg + e;
            xs[c][n] = X[((size_t)b * CH + c0 + c) * NSP + n0 + n];
        }
    }
    __syncthreads();

    // write transposed: thread owns (n = t>>2, 8 c's at cg=(t&3)*8)
    {
        const int n  = t >> 2;
        const int cg = (t & 3) * 8;
        float v[8];
#pragma unroll
        for (int e = 0; e < 8; ++e) v[e] = xs[cg + e][n];
        uint4 hi, lo;
        hi.x = cvt2(v[1], v[0]); hi.y = cvt2(v[3], v[2]);
        hi.z = cvt2(v[5], v[4]); hi.w = cvt2(v[7], v[6]);
        float2 g0 = h22f2(hi.x), g1 = h22f2(hi.y), g2 = h22f2(hi.z), g3 = h22f2(hi.w);
        lo.x = cvt2(v[1] - g0.y, v[0] - g0.x);
        lo.y = cvt2(v[3] - g1.y, v[2] - g1.x);
        lo.z = cvt2(v[5] - g2.y, v[4] - g2.x);
        lo.w = cvt2(v[7] - g3.y, v[6] - g3.x);
        size_t off = ((size_t)b * NSP + n0 + n) * CH + c0 + cg;
        *(uint4*)(Xh + off) = hi;
        *(uint4*)(Xl + off) = lo;
    }
}

// ---------------- 1x1 conv from prepped fp16 hi/lo input ----------------
// C[b,o,n] = sum_c W[o,c] X[b,n,c] + bias[o]; Markidis 3-term.
// grid (NSP/64, OC/64, B2), block 256
__global__ void __launch_bounds__(256) conv1x1p_kernel(
    const __half* __restrict__ Xh, const __half* __restrict__ Xl,
    const float* __restrict__ W, const float* __restrict__ bias,
    float* __restrict__ Cout, int OC, int IC)
{
    __shared__ __align__(16) __half Whs[64 * CSTR];
    __shared__ __align__(16) __half Wls[64 * CSTR];
    __shared__ __align__(16) __half Xhs[64 * CSTR];
    __shared__ __align__(16) __half Xls[64 * CSTR];

    const int t    = threadIdx.x;
    const int lane = t & 31;
    const int wid  = t >> 5;
    const int o0w  = (wid & 3) * 16;
    const int n0w  = (wid >> 2) * 32;
    const int r    = lane >> 2;
    const int cc   = lane & 3;

    const int n0 = blockIdx.x * 64;
    const int o0 = blockIdx.y * 64;
    const int b  = blockIdx.z;

    const __half* xh = Xh + ((size_t)b * NSP + n0) * IC;
    const __half* xl = Xl + ((size_t)b * NSP + n0) * IC;

    // X cp.async coords: 256 chunks per buffer, one per thread
    const int xrow = t >> 2;
    const int xcg  = (t & 3) * 8;

    float sacc[4][4];
#pragma unroll
    for (int nt = 0; nt < 4; ++nt)
#pragma unroll
        for (int e = 0; e < 4; ++e) sacc[nt][e] = 0.f;

    for (int c0 = 0; c0 < IC; c0 += 32) {
        // X tiles via cp.async (no transpose, no cvt)
        cp16(&Xhs[xrow * CSTR + xcg], xh + (size_t)xrow * IC + c0 + xcg);
        cp16(&Xls[xrow * CSTR + xcg], xl + (size_t)xrow * IC + c0 + xcg);
        cp_commit();
        // W tile [64 o][32 c], split in-loop (small)
#pragma unroll
        for (int e = 0; e < 2; ++e) {
            int idx = t + e * 256;
            int o  = idx >> 3;
            int c4 = (idx & 7) * 4;
            float4 f = *(const float4*)(W + (size_t)(o0 + o) * IC + c0 + c4);
            uint2 hi, lo;
            split4(f, hi, lo);
            *(uint2*)&Whs[o * CSTR + c4] = hi;
            *(uint2*)&Wls[o * CSTR + c4] = lo;
        }
        cp_wait0();
        __syncthreads();

#pragma unroll
        for (int ks = 0; ks < 2; ++ks) {
            const int arow = (o0w + (lane & 15)) * CSTR + ks * 16 + ((lane >> 4) << 3);
            uint32_t ah0, ah1, ah2, ah3, al0, al1, al2, al3;
            ldsm_x4(ah0, ah1, ah2, ah3, &Whs[arow]);
            ldsm_x4(al0, al1, al2, al3, &Wls[arow]);
#pragma unroll
            for (int p = 0; p < 2; ++p) {
                const int brow = (n0w + p * 16 + ((lane >> 4) << 3) + (lane & 7)) * CSTR
                               + ks * 16 + (lane & 8);
                uint32_t bh0, bh1, bh2, bh3, bl0, bl1, bl2, bl3;
                ldsm_x4(bh0, bh1, bh2, bh3, &Xhs[brow]);
                ldsm_x4(bl0, bl1, bl2, bl3, &Xls[brow]);
                mma16816(sacc[2 * p],     ah0, ah1, ah2, ah3, bh0, bh1);
                mma16816(sacc[2 * p + 1], ah0, ah1, ah2, ah3, bh2, bh3);
                mma16816(sacc[2 * p],     ah0, ah1, ah2, ah3, bl0, bl1);
                mma16816(sacc[2 * p + 1], ah0, ah1, ah2, ah3, bl2, bl3);
                mma16816(sacc[2 * p],     al0, al1, al2, al3, bh0, bh1);
                mma16816(sacc[2 * p + 1], al0, al1, al2, al3, bh2, bh3);
            }
        }
        __syncthreads();
    }

    const int o_lo = o0 + o0w + r;
    const int o_hi = o_lo + 8;
    const float blo = bias[o_lo];
    const float bhi = bias[o_hi];
    float* out_lo = Cout + ((size_t)b * OC + o_lo) * NSP + n0 + n0w;
    float* out_hi = Cout + ((size_t)b * OC + o_hi) * NSP + n0 + n0w;
#pragma unroll
    for (int nt = 0; nt < 4; ++nt) {
        int n = nt * 8 + 2 * cc;
        *(float2*)(out_lo + n) = make_float2(sacc[nt][0] + blo, sacc[nt][1] + blo);
        *(float2*)(out_hi + n) = make_float2(sacc[nt][2] + bhi, sacc[nt][3] + bhi);
    }
}

// ---------------- 3x3 depthwise conv; v channels emitted as fp16 (R9) ----------------
__global__ void __launch_bounds__(256) dwconv_kernel(
    const float* __restrict__ in, const float* __restrict__ wdw,
    const float* __restrict__ bias, float* __restrict__ out, __half* __restrict__ vh)
{
    const int bc = blockIdx.x;
    const int ch = bc % C3;
    const int b  = bc / C3;
    const float* p = in + (size_t)bc * NSP;

    float w9[9];
#pragma unroll
    for (int i = 0; i < 9; ++i) w9[i] = wdw[ch * 9 + i];

    const int idx = blockIdx.y * 256 + threadIdx.x;
    const int y = idx >> 6;
    const int x = idx & 63;

    float acc = bias[ch];
#pragma unroll
    for (int dy = -1; dy <= 1; ++dy) {
        int yy = y + dy;
        if (yy < 0 || yy > 63) continue;
#pragma unroll
        for (int dx = -1; dx <= 1; ++dx) {
            int xx = x + dx;
            if (xx < 0 || xx > 63) continue;
            acc += __ldg(p + yy * 64 + xx) * w9[(dy + 1) * 3 + (dx + 1)];
        }
    }
    if (ch < 2 * CH) {
        out[(size_t)bc * NSP + idx] = acc;
    } else {
        vh[((size_t)b * CH + (ch - 2 * CH)) * NSP + idx] = __float2half(acc);
    }
}

// ---------------- single-pass L2 norm -> fp16 [bh][n][48]; q and k via z-dim (R9) ----
__global__ void __launch_bounds__(128) normh_kernel(
    const float* __restrict__ qkv, __half* __restrict__ qh, __half* __restrict__ kh,
    const float* __restrict__ temp)
{
    const int which = blockIdx.z;
    const int bh    = blockIdx.y;
    const int b     = bh >> 2;
    const int head  = bh & 3;
    const int n     = blockIdx.x * 128 + threadIdx.x;

    const float* p = qkv + ((size_t)(b * C3) + which * CH + head * HD) * NSP + n;

    float v[HD];
    float s = 0.f;
#pragma unroll
    for (int d = 0; d < HD; ++d) {
        v[d] = p[(size_t)d * NSP];
        s += v[d] * v[d];
    }
    const float sc = (which ? 1.0f : temp[head] * L2E) / fmaxf(sqrtf(s), 1e-12f);

    __half* o = (which ? kh : qh) + ((size_t)bh * NSP + n) * HD;
#pragma unroll
    for (int g = 0; g < 6; ++g) {
        float a0 = v[g * 8 + 0] * sc, a1 = v[g * 8 + 1] * sc;
        float a2 = v[g * 8 + 2] * sc, a3 = v[g * 8 + 3] * sc;
        float a4 = v[g * 8 + 4] * sc, a5 = v[g * 8 + 5] * sc;
        float a6 = v[g * 8 + 6] * sc, a7 = v[g * 8 + 7] * sc;
        *(uint4*)(o + g * 8) = make_uint4(cvt2(a1, a0), cvt2(a3, a2), cvt2(a5, a4), cvt2(a7, a6));
    }
}

// ---------------- flash attention: R9 verbatim; epilogue emits fp16 hi/lo [n][c] ------
__global__ void __launch_bounds__(256, 2) attn_kernel(
    const __half* __restrict__ qh, const __half* __restrict__ kh,
    const __half* __restrict__ vh, const float* __restrict__ temp,
    __half* __restrict__ atth, __half* __restrict__ attl)
{
    __shared__ __align__(16) char arena[43008];
    __half* Qs = (__half*)arena;
    __half* KsBuf[2] = { (__half*)(arena + 14336), (__half*)(arena + 21504) };
    __half* VsBuf[2] = { (__half*)(arena + 28672), (__half*)(arena + 35584) };
    float*  lred = (float*)(arena + 42496);
    float*  Ored = (float*)arena;

    const int t    = threadIdx.x;
    const int lane = t & 31;
    const int wid  = t >> 5;
    const int wi   = wid & 3;
    const int wj   = wid >> 2;
    const int i0   = wi * 32;
    const int r    = lane >> 2;
    const int cc   = lane & 3;

    const int bh   = blockIdx.y;
    const int b    = bh >> 2;
    const int head = bh & 3;
    const int n0   = blockIdx.x * 128;

    const __half* qb = qh + (size_t)bh * NSP * HD;
    const __half* kb = kh + (size_t)bh * NSP * HD;
    const __half* vb = vh + ((size_t)b * CH + head * HD) * NSP;
    const float   cbias = fabsf(temp[head]) * L2E;

#pragma unroll
    for (int e = 0; e < 3; ++e) {
        int ch = t + e * 256, row = ch / 6, c = (ch % 6) * 8;
        cp16(&Qs[row * QKSTR + c], qb + ((size_t)(n0 + row)) * HD + c);
    }
    {
        int row = t / 6, c = (t % 6) * 8;
        cp16(&KsBuf[0][row * QKSTR + c], kb + (size_t)row * HD + c);
    }
    if (t < 128) {
        int ch = t + 256, row = ch / 6, c = (ch % 6) * 8;
        cp16(&KsBuf[0][row * QKSTR + c], kb + (size_t)row * HD + c);
    }
    {
        int row = t >> 3, c = (t & 7) * 8;
        cp16(&VsBuf[0][row * VSTR + c], vb + (size_t)row * NSP + c);
    }
    if (t < 128) {
        int ch = t + 256, row = ch >> 3, c = (ch & 7) * 8;
        cp16(&VsBuf[0][row * VSTR + c], vb + (size_t)row * NSP + c);
    }
    cp_commit();

    float oacc[2][6][4];
#pragma unroll
    for (int mt = 0; mt < 2; ++mt)
#pragma unroll
        for (int nt = 0; nt < 6; ++nt)
#pragma unroll
            for (int e = 0; e < 4; ++e) oacc[mt][nt][e] = 0.f;
    float l_lo[2] = {0.f, 0.f}, l_hi[2] = {0.f, 0.f};

    uint32_t qa[2][3][4];

    const int krow0 = t / 6,          kc0 = (t % 6) * 8;
    const int krow1 = (t + 256) / 6,  kc1 = ((t + 256) % 6) * 8;
    const int vrow0 = t >> 3,         vc0 = (t & 7) * 8;
    const int vrow1 = (t + 256) >> 3, vc1 = ((t + 256) & 7) * 8;

    for (int it = 0; it < NSP / 64; ++it) {
        const int cur = it & 1;
        const __half* Kc = KsBuf[cur];
        const __half* Vc = VsBuf[cur];
        const bool has_next = (it < NSP / 64 - 1);

        cp_wait0();
        __syncthreads();

        if (it == 0) {
#pragma unroll
            for (int mt = 0; mt < 2; ++mt)
#pragma unroll
                for (int ks = 0; ks < 3; ++ks)
                    ldsm_x4(qa[mt][ks][0], qa[mt][ks][1], qa[mt][ks][2], qa[mt][ks][3],
                            &Qs[(i0 + mt * 16 + (lane & 15)) * QKSTR + ks * 16 + ((lane >> 4) << 3)]);
        }

        if (has_next) {
            const int nb = cur ^ 1;
            const int m0n = (it + 1) * 64;
            cp16(&KsBuf[nb][krow0 * QKSTR + kc0], kb + ((size_t)(m0n + krow0)) * HD + kc0);
            if (t < 128)
                cp16(&KsBuf[nb][krow1 * QKSTR + kc1], kb + ((size_t)(m0n + krow1)) * HD + kc1);
            cp16(&VsBuf[nb][vrow0 * VSTR + vc0], vb + (size_t)vrow0 * NSP + m0n + vc0);
            if (t < 128)
                cp16(&VsBuf[nb][vrow1 * VSTR + vc1], vb + (size_t)vrow1 * NSP + m0n + vc1);
            cp_commit();
        }

        float sacc[2][4][4];
#pragma unroll
        for (int mt = 0; mt < 2; ++mt)
#pragma unroll
            for (int jj = 0; jj < 4; ++jj)
#pragma unroll
                for (int e = 0; e < 4; ++e) sacc[mt][jj][e] = 0.f;

#pragma unroll
        for (int ks = 0; ks < 3; ++ks) {
#pragma unroll
            for (int p = 0; p < 2; ++p) {
                uint32_t b0, b1, b2, b3;
                int row = wj * 32 + p * 16 + ((lane >> 4) << 3) + (lane & 7);
                int col = ks * 16 + (lane & 8);
                ldsm_x4(b0, b1, b2, b3, &Kc[row * QKSTR + col]);
#pragma unroll
                for (int mt = 0; mt < 2; ++mt) {
                    mma16816(sacc[mt][2 * p],     qa[mt][ks][0], qa[mt][ks][1],
                                                  qa[mt][ks][2], qa[mt][ks][3], b0, b1);
                    mma16816(sacc[mt][2 * p + 1], qa[mt][ks][0], qa[mt][ks][1],
                                                  qa[mt][ks][2], qa[mt][ks][3], b2, b3);
                }
            }
        }

        uint32_t plo[2][4], phi[2][4];
#pragma unroll
        for (int mt = 0; mt < 2; ++mt) {
            uint32_t sum_lo = 0, sum_hi = 0;
#pragma unroll
            for (int jj = 0; jj < 4; ++jj) {
                plo[mt][jj] = ex2h2(cvt2(sacc[mt][jj][1] - cbias, sacc[mt][jj][0] - cbias));
                phi[mt][jj] = ex2h2(cvt2(sacc[mt][jj][3] - cbias, sacc[mt][jj][2] - cbias));
                sum_lo = hadd2(sum_lo, plo[mt][jj]);
                sum_hi = hadd2(sum_hi, phi[mt][jj]);
            }
            float2 f0 = h22f2(sum_lo); l_lo[mt] += f0.x + f0.y;
            float2 f1 = h22f2(sum_hi); l_hi[mt] += f1.x + f1.y;
        }

#pragma unroll
        for (int nt = 0; nt < 6; ++nt) {
            uint32_t b0, b1, b2, b3;
            ldsm_x4(b0, b1, b2, b3,
                    &Vc[(nt * 8 + (lane & 7)) * VSTR + wj * 32 + ((lane >> 3) & 3) * 8]);
#pragma unroll
            for (int mt = 0; mt < 2; ++mt) {
                mma16816(oacc[mt][nt], plo[mt][0], phi[mt][0], plo[mt][1], phi[mt][1], b0, b1);
                mma16816(oacc[mt][nt], plo[mt][2], phi[mt][2], plo[mt][3], phi[mt][3], b2, b3);
            }
        }
        __syncthreads();
    }

    // ---- epilogue: reduce l; wj=1 stages; wj=0 combines + stores fp16 hi/lo [n][c] ----
#pragma unroll
    for (int mt = 0; mt < 2; ++mt) {
        l_lo[mt] += __shfl_xor_sync(0xffffffffu, l_lo[mt], 1);
        l_lo[mt] += __shfl_xor_sync(0xffffffffu, l_lo[mt], 2);
        l_hi[mt] += __shfl_xor_sync(0xffffffffu, l_hi[mt], 1);
        l_hi[mt] += __shfl_xor_sync(0xffffffffu, l_hi[mt], 2);
    }
    if (wj == 1) {
#pragma unroll
        for (int mt = 0; mt < 2; ++mt) {
            const int ib = i0 + mt * 16;
            if (cc == 0) {
                lred[ib + r]     = l_lo[mt];
                lred[ib + r + 8] = l_hi[mt];
            }
#pragma unroll
            for (int nt = 0; nt < 6; ++nt) {
                int d = nt * 8 + 2 * cc;
                *(float2*)&Ored[(ib + r) * ORST + d]     = make_float2(oacc[mt][nt][0], oacc[mt][nt][1]);
                *(float2*)&Ored[(ib + r + 8) * ORST + d] = make_float2(oacc[mt][nt][2], oacc[mt][nt][3]);
            }
        }
    }
    __syncthreads();
    if (wj == 0) {
        __half* oh = atth + ((size_t)b * NSP + n0) * CH + head * HD;
        __half* ol = attl + ((size_t)b * NSP + n0) * CH + head * HD;
#pragma unroll
        for (int mt = 0; mt < 2; ++mt) {
            const int ib = i0 + mt * 16;
            const float linv_lo = 1.f / (l_lo[mt] + lred[ib + r]);
            const float linv_hi = 1.f / (l_hi[mt] + lred[ib + r + 8]);
#pragma unroll
            for (int nt = 0; nt < 6; ++nt) {
                int d = nt * 8 + 2 * cc;
                float2 p0 = *(const float2*)&Ored[(ib + r) * ORST + d];
                float2 p1 = *(const float2*)&Ored[(ib + r + 8) * ORST + d];
                float v0 = (oacc[mt][nt][0] + p0.x) * linv_lo;
                float v1 = (oacc[mt][nt][1] + p0.y) * linv_lo;
                float v2 = (oacc[mt][nt][2] + p1.x) * linv_hi;
                float v3 = (oacc[mt][nt][3] + p1.y) * linv_hi;
                uint32_t h0 = cvt2(v1, v0);
                uint32_t h1 = cvt2(v3, v2);
                float2 g0 = h22f2(h0), g1 = h22f2(h1);
                uint32_t l0 = cvt2(v1 - g0.y, v0 - g0.x);
                uint32_t l1 = cvt2(v3 - g1.y, v2 - g1.x);
                *(uint32_t*)&oh[(size_t)(ib + r) * CH + d]     = h0;
                *(uint32_t*)&ol[(size_t)(ib + r) * CH + d]     = l0;
                *(uint32_t*)&oh[(size_t)(ib + r + 8) * CH + d] = h1;
                *(uint32_t*)&ol[(size_t)(ib + r + 8) * CH + d] = l1;
            }
        }
    }
}

// ---------------- launcher ----------------
extern "C" void kernel_launch(void* const* d_in, const int* in_sizes, int n_in,
                              void* d_out, int out_size)
{
    const float* x      = (const float*)d_in[0];
    const float* w_qkv  = (const float*)d_in[1];
    const float* b_qkv  = (const float*)d_in[2];
    const float* w_dw   = (const float*)d_in[3];
    const float* b_dw   = (const float*)d_in[4];
    const float* w_proj = (const float*)d_in[5];
    const float* b_proj = (const float*)d_in[6];
    const float* temp   = (const float*)d_in[7];
    float* out = (float*)d_out;

    float*  qkv1; cudaGetSymbolAddress((void**)&qkv1, g_qkv);
    float*  qkv2; cudaGetSymbolAddress((void**)&qkv2, g_qkv2);
    __half* xhp;  cudaGetSymbolAddress((void**)&xhp,  g_xh);
    __half* xlp;  cudaGetSymbolAddress((void**)&xlp,  g_xl);
    __half* ahp;  cudaGetSymbolAddress((void**)&ahp,  g_ah);
    __half* alp;  cudaGetSymbolAddress((void**)&alp,  g_al);
    __half* qhp;  cudaGetSymbolAddress((void**)&qhp,  g_qh);
    __half* khp;  cudaGetSymbolAddress((void**)&khp,  g_kh);
    __half* vhp;  cudaGetSymbolAddress((void**)&vhp,  g_vh);

    xprep_kernel<<<dim3(NSP / 64, CH / 32, B2), 256>>>(x, xhp, xlp);
    conv1x1p_kernel<<<dim3(NSP / 64, C3 / 64, B2), 256>>>(xhp, xlp, w_qkv, b_qkv, qkv1, C3, CH);
    dwconv_kernel<<<dim3(B2 * C3, NSP / 256), 256>>>(qkv1, w_dw, b_dw, qkv2, vhp);
    normh_kernel<<<dim3(NSP / 128, B2 * HEADS, 2), 128>>>(qkv2, qhp, khp, temp);
    attn_kernel<<<dim3(NSP / 128, B2 * HEADS), 256>>>(qhp, khp, vhp, temp, ahp, alp);
    conv1x1p_kernel<<<dim3(NSP / 64, CH / 64, B2), 256>>>(ahp, alp, w_proj, b_proj, out, CH, CH);
}

// round 15
// speedup vs baseline: 1.5510x; 1.1088x over previous
#include <cuda_runtime.h>
#include <cuda_fp16.h>
#include <cstdint>

#define B2     2
#define CH     192
#define C3     (3*CH)
#define HEADS  4
#define HD     48
#define NSP    4096
#define L2E    1.44269504f

#define QKSTR 56   // half stride: 7 16B-chunks (odd mod 8) -> ldmatrix conflict-free
#define VSTR  72   // 9 chunks
#define CSTR  40   // conv tiles: 5 chunks
#define ORST  52   // O-staging stride (52 ≡ 20 mod 32 -> bank-bijective)

// ---------------- scratch ----------------
__device__ float  g_qkv [B2 * C3 * NSP];
__device__ float  g_qkv2[B2 * C3 * NSP];
__device__ float  g_att [B2 * CH * NSP];
__device__ __half g_qh  [B2 * HEADS * NSP * HD];
__device__ __half g_kh  [B2 * HEADS * NSP * HD];
__device__ __half g_vh  [B2 * CH * NSP];

// ---------------- asm helpers ----------------
__device__ __forceinline__ uint32_t sptr(const void* p) {
    return (uint32_t)__cvta_generic_to_shared(p);
}
__device__ __forceinline__ void ldsm_x4(uint32_t& r0, uint32_t& r1, uint32_t& r2, uint32_t& r3,
                                        const __half* p) {
    asm volatile("ldmatrix.sync.aligned.m8n8.x4.shared.b16 {%0,%1,%2,%3}, [%4];"
                 : "=r"(r0), "=r"(r1), "=r"(r2), "=r"(r3) : "r"(sptr(p)));
}
__device__ __forceinline__ void mma16816(float c[4],
                                         uint32_t a0, uint32_t a1, uint32_t a2, uint32_t a3,
                                         uint32_t b0, uint32_t b1) {
    asm volatile(
        "mma.sync.aligned.m16n8k16.row.col.f32.f16.f16.f32 "
        "{%0,%1,%2,%3}, {%4,%5,%6,%7}, {%8,%9}, {%0,%1,%2,%3};"
        : "+f"(c[0]), "+f"(c[1]), "+f"(c[2]), "+f"(c[3])
        : "r"(a0), "r"(a1), "r"(a2), "r"(a3), "r"(b0), "r"(b1));
}
__device__ __forceinline__ uint32_t cvt2(float hi, float lo) {
    uint32_t r;
    asm("cvt.rn.f16x2.f32 %0, %1, %2;" : "=r"(r) : "f"(hi), "f"(lo));
    return r;
}
__device__ __forceinline__ uint32_t ex2h2(uint32_t x) {
    uint32_t r;
    asm("ex2.approx.f16x2 %0, %1;" : "=r"(r) : "r"(x));
    return r;
}
__device__ __forceinline__ uint32_t hadd2(uint32_t a, uint32_t b) {
    uint32_t r;
    asm("add.rn.f16x2 %0, %1, %2;" : "=r"(r) : "r"(a), "r"(b));
    return r;
}
__device__ __forceinline__ float2 h22f2(uint32_t u) {
    __half2 h = *reinterpret_cast<__half2*>(&u);
    return __half22float2(h);
}
__device__ __forceinline__ void split4(float4 f, uint2& hi, uint2& lo) {
    hi = make_uint2(cvt2(f.y, f.x), cvt2(f.w, f.z));
    float2 g0 = h22f2(hi.x), g1 = h22f2(hi.y);
    lo = make_uint2(cvt2(f.y - g0.y, f.x - g0.x), cvt2(f.w - g1.y, f.z - g1.x));
}
__device__ __forceinline__ void cp16(const __half* smem_dst, const __half* gsrc) {
    asm volatile("cp.async.cg.shared.global [%0], [%1], 16;"
                 :: "r"(sptr(smem_dst)), "l"(gsrc));
}
__device__ __forceinline__ void cp_commit() { asm volatile("cp.async.commit_group;"); }
__device__ __forceinline__ void cp_wait0()  { asm volatile("cp.async.wait_group 0;"); }

// ---------------- 1x1 conv as split-fp16 tensor GEMM (R9 verbatim) ----------------
__global__ void __launch_bounds__(256) conv1x1_tc_kernel(
    const float* __restrict__ X, const float* __restrict__ W,
    const float* __restrict__ bias, float* __restrict__ Cout,
    int OC, int IC)
{
    __shared__ __align__(16) __half Wh[64 * CSTR];
    __shared__ __align__(16) __half Wl[64 * CSTR];
    __shared__ __align__(16) __half Xh[64 * CSTR];
    __shared__ __align__(16) __half Xl[64 * CSTR];

    const int t    = threadIdx.x;
    const int lane = t & 31;
    const int wid  = t >> 5;
    const int o0w  = (wid & 3) * 16;
    const int n0w  = (wid >> 2) * 32;
    const int r    = lane >> 2;
    const int cc   = lane & 3;

    const int n0 = blockIdx.x * 64;
    const int o0 = blockIdx.y * 64;
    const int b  = blockIdx.z;

    const float* Xb = X + ((size_t)b * IC) * NSP + n0;

    const int nX = t & 63;
    const int cg = (t >> 6) * 4;

    float sacc[4][4];
#pragma unroll
    for (int nt = 0; nt < 4; ++nt)
#pragma unroll
        for (int e = 0; e < 4; ++e) sacc[nt][e] = 0.f;

    for (int c0 = 0; c0 < IC; c0 += 32) {
#pragma unroll
        for (int e = 0; e < 2; ++e) {
            int idx = t + e * 256;
            int o  = idx >> 3;
            int c4 = (idx & 7) * 4;
            float4 f = *(const float4*)(W + (size_t)(o0 + o) * IC + c0 + c4);
            uint2 hi, lo;
            split4(f, hi, lo);
            *(uint2*)&Wh[o * CSTR + c4] = hi;
            *(uint2*)&Wl[o * CSTR + c4] = lo;
        }
#pragma unroll
        for (int e = 0; e < 2; ++e) {
            int c = cg + e * 16;
            float4 f;
            f.x = Xb[(size_t)(c0 + c + 0) * NSP + nX];
            f.y = Xb[(size_t)(c0 + c + 1) * NSP + nX];
            f.z = Xb[(size_t)(c0 + c + 2) * NSP + nX];
            f.w = Xb[(size_t)(c0 + c + 3) * NSP + nX];
            uint2 hi, lo;
            split4(f, hi, lo);
            *(uint2*)&Xh[nX * CSTR + c] = hi;
            *(uint2*)&Xl[nX * CSTR + c] = lo;
        }
        __syncthreads();

#pragma unroll
        for (int ks = 0; ks < 2; ++ks) {
            const int arow = (o0w + (lane & 15)) * CSTR + ks * 16 + ((lane >> 4) << 3);
            uint32_t ah0, ah1, ah2, ah3, al0, al1, al2, al3;
            ldsm_x4(ah0, ah1, ah2, ah3, &Wh[arow]);
            ldsm_x4(al0, al1, al2, al3, &Wl[arow]);
#pragma unroll
            for (int p = 0; p < 2; ++p) {
                const int brow = (n0w + p * 16 + ((lane >> 4) << 3) + (lane & 7)) * CSTR
                               + ks * 16 + (lane & 8);
                uint32_t bh0, bh1, bh2, bh3, bl0, bl1, bl2, bl3;
                ldsm_x4(bh0, bh1, bh2, bh3, &Xh[brow]);
                ldsm_x4(bl0, bl1, bl2, bl3, &Xl[brow]);
                mma16816(sacc[2 * p],     ah0, ah1, ah2, ah3, bh0, bh1);
                mma16816(sacc[2 * p + 1], ah0, ah1, ah2, ah3, bh2, bh3);
                mma16816(sacc[2 * p],     ah0, ah1, ah2, ah3, bl0, bl1);
                mma16816(sacc[2 * p + 1], ah0, ah1, ah2, ah3, bl2, bl3);
                mma16816(sacc[2 * p],     al0, al1, al2, al3, bh0, bh1);
                mma16816(sacc[2 * p + 1], al0, al1, al2, al3, bh2, bh3);
            }
        }
        __syncthreads();
    }

    const int o_lo = o0 + o0w + r;
    const int o_hi = o_lo + 8;
    const float blo = bias[o_lo];
    const float bhi = bias[o_hi];
    float* out_lo = Cout + ((size_t)b * OC + o_lo) * NSP + n0 + n0w;
    float* out_hi = Cout + ((size_t)b * OC + o_hi) * NSP + n0 + n0w;
#pragma unroll
    for (int nt = 0; nt < 4; ++nt) {
        int n = nt * 8 + 2 * cc;
        *(float2*)(out_lo + n) = make_float2(sacc[nt][0] + blo, sacc[nt][1] + blo);
        *(float2*)(out_hi + n) = make_float2(sacc[nt][2] + bhi, sacc[nt][3] + bhi);
    }
}

// ---------------- 3x3 depthwise conv, VECTORIZED: 4 pixels/thread ----------------
// grid: (B2*C3, NSP/1024), block 256. Per row: 1 float4 + 2 edge scalars (9 LDG / 4 out).
__global__ void __launch_bounds__(256) dwconv_kernel(
    const float* __restrict__ in, const float* __restrict__ wdw,
    const float* __restrict__ bias, float* __restrict__ out, __half* __restrict__ vh)
{
    const int bc = blockIdx.x;
    const int ch = bc % C3;
    const int b  = bc / C3;
    const float* p = in + (size_t)bc * NSP;

    float w9[9];
#pragma unroll
    for (int i = 0; i < 9; ++i) w9[i] = wdw[ch * 9 + i];

    const int n4 = (blockIdx.y * 256 + threadIdx.x) * 4;
    const int y  = n4 >> 6;
    const int x0 = n4 & 63;
    const bool has_l = (x0 > 0);
    const bool has_r = (x0 + 4 < 64);

    const float bv = bias[ch];
    float acc[4] = {bv, bv, bv, bv};

#pragma unroll
    for (int dy = -1; dy <= 1; ++dy) {
        const int yy = y + dy;
        if (yy < 0 || yy > 63) continue;
        const float* row = p + yy * 64 + x0;
        float4 c4 = *(const float4*)row;
        float vl = has_l ? row[-1] : 0.f;
        float vr = has_r ? row[4]  : 0.f;
        const float wl = w9[(dy + 1) * 3 + 0];
        const float wc = w9[(dy + 1) * 3 + 1];
        const float wr = w9[(dy + 1) * 3 + 2];
        // taps in dx order (matches original accumulation order)
        acc[0] += wl * vl;   acc[0] += wc * c4.x; acc[0] += wr * c4.y;
        acc[1] += wl * c4.x; acc[1] += wc * c4.y; acc[1] += wr * c4.z;
        acc[2] += wl * c4.y; acc[2] += wc * c4.z; acc[2] += wr * c4.w;
        acc[3] += wl * c4.z; acc[3] += wc * c4.w; acc[3] += wr * vr;
    }

    if (ch < 2 * CH) {
        *(float4*)(out + (size_t)bc * NSP + n4) =
            make_float4(acc[0], acc[1], acc[2], acc[3]);
    } else {
        uint2 hv = make_uint2(cvt2(acc[1], acc[0]), cvt2(acc[3], acc[2]));
        *(uint2*)(vh + ((size_t)b * CH + (ch - 2 * CH)) * NSP + n4) = hv;
    }
}

// ---------------- single-pass L2 norm -> fp16 [bh][n][48]; q and k via z-dim (R9) ----
__global__ void __launch_bounds__(128) normh_kernel(
    const float* __restrict__ qkv, __half* __restrict__ qh, __half* __restrict__ kh,
    const float* __restrict__ temp)
{
    const int which = blockIdx.z;        // 0 = q, 1 = k
    const int bh    = blockIdx.y;
    const int b     = bh >> 2;
    const int head  = bh & 3;
    const int n     = blockIdx.x * 128 + threadIdx.x;

    const float* p = qkv + ((size_t)(b * C3) + which * CH + head * HD) * NSP + n;

    float v[HD];
    float s = 0.f;
#pragma unroll
    for (int d = 0; d < HD; ++d) {
        v[d] = p[(size_t)d * NSP];
        s += v[d] * v[d];
    }
    const float sc = (which ? 1.0f : temp[head] * L2E) / fmaxf(sqrtf(s), 1e-12f);

    __half* o = (which ? kh : qh) + ((size_t)bh * NSP + n) * HD;
#pragma unroll
    for (int g = 0; g < 6; ++g) {
        float a0 = v[g * 8 + 0] * sc, a1 = v[g * 8 + 1] * sc;
        float a2 = v[g * 8 + 2] * sc, a3 = v[g * 8 + 3] * sc;
        float a4 = v[g * 8 + 4] * sc, a5 = v[g * 8 + 5] * sc;
        float a6 = v[g * 8 + 6] * sc, a7 = v[g * 8 + 7] * sc;
        *(uint4*)(o + g * 8) = make_uint4(cvt2(a1, a0), cvt2(a3, a2), cvt2(a5, a4), cvt2(a7, a6));
    }
}

// ---------------- flash attention (R9 verbatim) ----------------
__global__ void __launch_bounds__(256, 2) attn_kernel(
    const __half* __restrict__ qh, const __half* __restrict__ kh,
    const __half* __restrict__ vh, const float* __restrict__ temp,
    float* __restrict__ out)
{
    __shared__ __align__(16) char arena[43008];
    __half* Qs = (__half*)arena;
    __half* KsBuf[2] = { (__half*)(arena + 14336), (__half*)(arena + 21504) };
    __half* VsBuf[2] = { (__half*)(arena + 28672), (__half*)(arena + 35584) };
    float*  lred = (float*)(arena + 42496);
    float*  Ored = (float*)arena;

    const int t    = threadIdx.x;
    const int lane = t & 31;
    const int wid  = t >> 5;
    const int wi   = wid & 3;
    const int wj   = wid >> 2;
    const int i0   = wi * 32;
    const int r    = lane >> 2;
    const int cc   = lane & 3;

    const int bh   = blockIdx.y;
    const int b    = bh >> 2;
    const int head = bh & 3;
    const int n0   = blockIdx.x * 128;

    const __half* qb = qh + (size_t)bh * NSP * HD;
    const __half* kb = kh + (size_t)bh * NSP * HD;
    const __half* vb = vh + ((size_t)b * CH + head * HD) * NSP;
    const float   cbias = fabsf(temp[head]) * L2E;

#pragma unroll
    for (int e = 0; e < 3; ++e) {
        int ch = t + e * 256, row = ch / 6, c = (ch % 6) * 8;
        cp16(&Qs[row * QKSTR + c], qb + ((size_t)(n0 + row)) * HD + c);
    }
    {
        int row = t / 6, c = (t % 6) * 8;
        cp16(&KsBuf[0][row * QKSTR + c], kb + (size_t)row * HD + c);
    }
    if (t < 128) {
        int ch = t + 256, row = ch / 6, c = (ch % 6) * 8;
        cp16(&KsBuf[0][row * QKSTR + c], kb + (size_t)row * HD + c);
    }
    {
        int row = t >> 3, c = (t & 7) * 8;
        cp16(&VsBuf[0][row * VSTR + c], vb + (size_t)row * NSP + c);
    }
    if (t < 128) {
        int ch = t + 256, row = ch >> 3, c = (ch & 7) * 8;
        cp16(&VsBuf[0][row * VSTR + c], vb + (size_t)row * NSP + c);
    }
    cp_commit();

    float oacc[2][6][4];
#pragma unroll
    for (int mt = 0; mt < 2; ++mt)
#pragma unroll
        for (int nt = 0; nt < 6; ++nt)
#pragma unroll
            for (int e = 0; e < 4; ++e) oacc[mt][nt][e] = 0.f;
    float l_lo[2] = {0.f, 0.f}, l_hi[2] = {0.f, 0.f};

    uint32_t qa[2][3][4];

    const int krow0 = t / 6,          kc0 = (t % 6) * 8;
    const int krow1 = (t + 256) / 6,  kc1 = ((t + 256) % 6) * 8;
    const int vrow0 = t >> 3,         vc0 = (t & 7) * 8;
    const int vrow1 = (t + 256) >> 3, vc1 = ((t + 256) & 7) * 8;

    for (int it = 0; it < NSP / 64; ++it) {
        const int cur = it & 1;
        const __half* Kc = KsBuf[cur];
        const __half* Vc = VsBuf[cur];
        const bool has_next = (it < NSP / 64 - 1);

        cp_wait0();
        __syncthreads();

        if (it == 0) {
#pragma unroll
            for (int mt = 0; mt < 2; ++mt)
#pragma unroll
                for (int ks = 0; ks < 3; ++ks)
                    ldsm_x4(qa[mt][ks][0], qa[mt][ks][1], qa[mt][ks][2], qa[mt][ks][3],
                            &Qs[(i0 + mt * 16 + (lane & 15)) * QKSTR + ks * 16 + ((lane >> 4) << 3)]);
        }

        if (has_next) {
            const int nb = cur ^ 1;
            const int m0n = (it + 1) * 64;
            cp16(&KsBuf[nb][krow0 * QKSTR + kc0], kb + ((size_t)(m0n + krow0)) * HD + kc0);
            if (t < 128)
                cp16(&KsBuf[nb][krow1 * QKSTR + kc1], kb + ((size_t)(m0n + krow1)) * HD + kc1);
            cp16(&VsBuf[nb][vrow0 * VSTR + vc0], vb + (size_t)vrow0 * NSP + m0n + vc0);
            if (t < 128)
                cp16(&VsBuf[nb][vrow1 * VSTR + vc1], vb + (size_t)vrow1 * NSP + m0n + vc1);
            cp_commit();
        }

        float sacc[2][4][4];
#pragma unroll
        for (int mt = 0; mt < 2; ++mt)
#pragma unroll
            for (int jj = 0; jj < 4; ++jj)
#pragma unroll
                for (int e = 0; e < 4; ++e) sacc[mt][jj][e] = 0.f;

#pragma unroll
        for (int ks = 0; ks < 3; ++ks) {
#pragma unroll
            for (int p = 0; p < 2; ++p) {
                uint32_t b0, b1, b2, b3;
                int row = wj * 32 + p * 16 + ((lane >> 4) << 3) + (lane & 7);
                int col = ks * 16 + (lane & 8);
                ldsm_x4(b0, b1, b2, b3, &Kc[row * QKSTR + col]);
#pragma unroll
                for (int mt = 0; mt < 2; ++mt) {
                    mma16816(sacc[mt][2 * p],     qa[mt][ks][0], qa[mt][ks][1],
                                                  qa[mt][ks][2], qa[mt][ks][3], b0, b1);
                    mma16816(sacc[mt][2 * p + 1], qa[mt][ks][0], qa[mt][ks][1],
                                                  qa[mt][ks][2], qa[mt][ks][3], b2, b3);
                }
            }
        }

        uint32_t plo[2][4], phi[2][4];
#pragma unroll
        for (int mt = 0; mt < 2; ++mt) {
            uint32_t sum_lo = 0, sum_hi = 0;
#pragma unroll
            for (int jj = 0; jj < 4; ++jj) {
                plo[mt][jj] = ex2h2(cvt2(sacc[mt][jj][1] - cbias, sacc[mt][jj][0] - cbias));
                phi[mt][jj] = ex2h2(cvt2(sacc[mt][jj][3] - cbias, sacc[mt][jj][2] - cbias));
                sum_lo = hadd2(sum_lo, plo[mt][jj]);
                sum_hi = hadd2(sum_hi, phi[mt][jj]);
            }
            float2 f0 = h22f2(sum_lo); l_lo[mt] += f0.x + f0.y;
            float2 f1 = h22f2(sum_hi); l_hi[mt] += f1.x + f1.y;
        }

#pragma unroll
        for (int nt = 0; nt < 6; ++nt) {
            uint32_t b0, b1, b2, b3;
            ldsm_x4(b0, b1, b2, b3,
                    &Vc[(nt * 8 + (lane & 7)) * VSTR + wj * 32 + ((lane >> 3) & 3) * 8]);
#pragma unroll
            for (int mt = 0; mt < 2; ++mt) {
                mma16816(oacc[mt][nt], plo[mt][0], phi[mt][0], plo[mt][1], phi[mt][1], b0, b1);
                mma16816(oacc[mt][nt], plo[mt][2], phi[mt][2], plo[mt][3], phi[mt][3], b2, b3);
            }
        }
        __syncthreads();
    }

#pragma unroll
    for (int mt = 0; mt < 2; ++mt) {
        l_lo[mt] += __shfl_xor_sync(0xffffffffu, l_lo[mt], 1);
        l_lo[mt] += __shfl_xor_sync(0xffffffffu, l_lo[mt], 2);
        l_hi[mt] += __shfl_xor_sync(0xffffffffu, l_hi[mt], 1);
        l_hi[mt] += __shfl_xor_sync(0xffffffffu, l_hi[mt], 2);
    }
    if (wj == 1) {
#pragma unroll
        for (int mt = 0; mt < 2; ++mt) {
            const int ib = i0 + mt * 16;
            if (cc == 0) {
                lred[ib + r]     = l_lo[mt];
                lred[ib + r + 8] = l_hi[mt];
            }
#pragma unroll
            for (int nt = 0; nt < 6; ++nt) {
                int d = nt * 8 + 2 * cc;
                *(float2*)&Ored[(ib + r) * ORST + d]     = make_float2(oacc[mt][nt][0], oacc[mt][nt][1]);
                *(float2*)&Ored[(ib + r + 8) * ORST + d] = make_float2(oacc[mt][nt][2], oacc[mt][nt][3]);
            }
        }
    }
    __syncthreads();
    if (wj == 0) {
        float* ob = out + ((size_t)(b * CH) + head * HD) * NSP + n0;
#pragma unroll
        for (int mt = 0; mt < 2; ++mt) {
            const int ib = i0 + mt * 16;
            const float linv_lo = 1.f / (l_lo[mt] + lred[ib + r]);
            const float linv_hi = 1.f / (l_hi[mt] + lred[ib + r + 8]);
#pragma unroll
            for (int nt = 0; nt < 6; ++nt) {
                int d = nt * 8 + 2 * cc;
                float2 p0 = *(const float2*)&Ored[(ib + r) * ORST + d];
                float2 p1 = *(const float2*)&Ored[(ib + r + 8) * ORST + d];
                ob[(size_t)d * NSP + ib + r]           = (oacc[mt][nt][0] + p0.x) * linv_lo;
                ob[(size_t)(d + 1) * NSP + ib + r]     = (oacc[mt][nt][1] + p0.y) * linv_lo;
                ob[(size_t)d * NSP + ib + r + 8]       = (oacc[mt][nt][2] + p1.x) * linv_hi;
                ob[(size_t)(d + 1) * NSP + ib + r + 8] = (oacc[mt][nt][3] + p1.y) * linv_hi;
            }
        }
    }
}

// ---------------- launcher (R9 set, dwconv grid updated for 4 px/thread) -------------
extern "C" void kernel_launch(void* const* d_in, const int* in_sizes, int n_in,
                              void* d_out, int out_size)
{
    const float* x      = (const float*)d_in[0];
    const float* w_qkv  = (const float*)d_in[1];
    const float* b_qkv  = (const float*)d_in[2];
    const float* w_dw   = (const float*)d_in[3];
    const float* b_dw   = (const float*)d_in[4];
    const float* w_proj = (const float*)d_in[5];
    const float* b_proj = (const float*)d_in[6];
    const float* temp   = (const float*)d_in[7];
    float* out = (float*)d_out;

    float*  qkv1; cudaGetSymbolAddress((void**)&qkv1, g_qkv);
    float*  qkv2; cudaGetSymbolAddress((void**)&qkv2, g_qkv2);
    float*  att;  cudaGetSymbolAddress((void**)&att,  g_att);
    __half* qhp;  cudaGetSymbolAddress((void**)&qhp,  g_qh);
    __half* khp;  cudaGetSymbolAddress((void**)&khp,  g_kh);
    __half* vhp;  cudaGetSymbolAddress((void**)&vhp,  g_vh);

    conv1x1_tc_kernel<<<dim3(NSP / 64, C3 / 64, B2), 256>>>(x, w_qkv, b_qkv, qkv1, C3, CH);
    dwconv_kernel<<<dim3(B2 * C3, NSP / 1024), 256>>>(qkv1, w_dw, b_dw, qkv2, vhp);
    normh_kernel<<<dim3(NSP / 128, B2 * HEADS, 2), 128>>>(qkv2, qhp, khp, temp);
    attn_kernel<<<dim3(NSP / 128, B2 * HEADS), 256>>>(qhp, khp, vhp, temp, att);
    conv1x1_tc_kernel<<<dim3(NSP / 64, CH / 64, B2), 256>>>(att, w_proj, b_proj, out, CH, CH);
}